// round 4
// baseline (speedup 1.0000x reference)
#include <cuda_runtime.h>
#include <cstdint>

// Problem dims
#define B_    128
#define T_    600
#define U_    96
#define K_    10
#define CD_   80
#define S_    512
#define OUT_  121     // 1 + 6*M
#define D1_   83      // 3 + CDIM
#define D2_   595     // 3 + S + CDIM

// Scan kernel config: G batches per CTA, each of NT_ threads owns 2 output cols
#define G_    2
#define NCTA_ (B_ / G_)   // 64 CTAs
#define NT_   256          // 256 threads x 2 cols = 512 outputs

// Output head config
#define ROWS_ 16

// h3 scratch: [B][T][S] fp32 (row index b*T + t matches reference reshape)
__device__ float g_ys[(size_t)B_ * T_ * S_];

__device__ __forceinline__ float sigf(float x) { return 1.0f / (1.0f + expf(-x)); }

// 8 accumulators: {gate j, gate k} x {batch 0, batch 1} x {col c, col c+1}
struct Acc {
    float j0x, j0y, j1x, j1y;
    float k0x, k0y, k1x, k1y;
};

// Accumulate one input span (N rows) of a dual-gate matvec for 2 batches,
// 2 consecutive output columns per thread. Weights streamed via .cg (L2-only)
// so L1 stays reserved for c_vec / W_win.
template<int N>
__device__ __forceinline__ void span(const float* __restrict__ Wj,
                                     const float* __restrict__ Wk,
                                     const float* a0, const float* a1,
                                     int c, Acc& A)
{
#pragma unroll 8
    for (int i = 0; i < N; ++i) {
        float2 wj = __ldcg(reinterpret_cast<const float2*>(Wj + i * S_ + c));
        float2 wk = __ldcg(reinterpret_cast<const float2*>(Wk + i * S_ + c));
        float v0 = a0[i];
        float v1 = a1[i];
        A.j0x = fmaf(v0, wj.x, A.j0x);  A.j0y = fmaf(v0, wj.y, A.j0y);
        A.j1x = fmaf(v1, wj.x, A.j1x);  A.j1y = fmaf(v1, wj.y, A.j1y);
        A.k0x = fmaf(v0, wk.x, A.k0x);  A.k0y = fmaf(v0, wk.y, A.k0y);
        A.k1x = fmaf(v1, wk.x, A.k1x);  A.k1y = fmaf(v1, wk.y, A.k1y);
    }
}

// Gated cell epilogue: h_new = sig(j)*(1-h) + (1-sig(k))*h
__device__ __forceinline__ void cell_update(const Acc& A,
                                            const float* hg0, const float* hg1, int c,
                                            float& n00, float& n01, float& n10, float& n11)
{
    float h00 = hg0[c], h01 = hg0[c + 1], h10 = hg1[c], h11 = hg1[c + 1];
    n00 = sigf(A.j0x) * (1.f - h00) + (1.f - sigf(A.k0x)) * h00;
    n01 = sigf(A.j0y) * (1.f - h01) + (1.f - sigf(A.k0y)) * h01;
    n10 = sigf(A.j1x) * (1.f - h10) + (1.f - sigf(A.k1x)) * h10;
    n11 = sigf(A.j1y) * (1.f - h11) + (1.f - sigf(A.k1y)) * h11;
}

__global__ void __launch_bounds__(NT_)
scan_kernel(const float* __restrict__ x,
            const float* __restrict__ c_vec,
            const float* __restrict__ W_jx1, const float* __restrict__ b_jx1,
            const float* __restrict__ W_jh1, const float* __restrict__ b_jh1,
            const float* __restrict__ W_kx1, const float* __restrict__ b_kx1,
            const float* __restrict__ W_kh1, const float* __restrict__ b_kh1,
            const float* __restrict__ W_jx2, const float* __restrict__ b_jx2,
            const float* __restrict__ W_jh2, const float* __restrict__ b_jh2,
            const float* __restrict__ W_kx2, const float* __restrict__ b_kx2,
            const float* __restrict__ W_kh2, const float* __restrict__ b_kh2,
            const float* __restrict__ W_win, const float* __restrict__ b_win)
{
    __shared__ float h1s[G_][S_];
    __shared__ float h2s[G_][S_];
    __shared__ float h3s[G_][S_];
    __shared__ float wsm[G_][CD_];
    __shared__ float phism[G_][U_];
    __shared__ float kgsm[G_][3 * K_];
    __shared__ float kappasm[G_][K_];
    __shared__ float alsm[G_][K_];
    __shared__ float besm[G_][K_];
    __shared__ float xts[G_][4];

    const int tid = threadIdx.x;
    const int c   = tid * 2;           // output columns c, c+1
    const int g0  = blockIdx.x * G_;   // global batch base

    // zero state
    for (int idx = tid; idx < G_ * S_; idx += NT_) {
        (&h1s[0][0])[idx] = 0.f;
        (&h2s[0][0])[idx] = 0.f;
        (&h3s[0][0])[idx] = 0.f;
    }
    for (int idx = tid; idx < G_ * CD_; idx += NT_) (&wsm[0][0])[idx] = 0.f;
    if (tid < G_ * K_) (&kappasm[0][0])[tid] = 0.f;
    __syncthreads();

    // per-thread bias preload (constant across steps); reference adds both biases
    const float bj1_0 = b_jx1[c] + b_jh1[c],     bj1_1 = b_jx1[c + 1] + b_jh1[c + 1];
    const float bk1_0 = b_kx1[c] + b_kh1[c],     bk1_1 = b_kx1[c + 1] + b_kh1[c + 1];
    const float bj2_0 = b_jx2[c] + b_jh2[c],     bj2_1 = b_jx2[c + 1] + b_jh2[c + 1];
    const float bk2_0 = b_kx2[c] + b_kh2[c],     bk2_1 = b_kx2[c + 1] + b_kh2[c + 1];

    // pre-offset weight row bases for span parts
    const float* Wjx1_w = W_jx1 + 3 * S_;     // in1 = [xt(3), w(80)]
    const float* Wkx1_w = W_kx1 + 3 * S_;
    const float* Wjx2_h = W_jx2 + 3 * S_;     // in2/in3 = [xt(3), h(512), w(80)]
    const float* Wkx2_h = W_kx2 + 3 * S_;
    const float* Wjx2_w = W_jx2 + 515 * S_;
    const float* Wkx2_w = W_kx2 + 515 * S_;

    for (int t = 0; t < T_; ++t) {
        // load x_t for both batches
        if (tid < G_ * 3) {
            int g = tid / 3, i = tid % 3;
            xts[g][i] = x[((size_t)(g0 + g) * T_ + t) * 3 + i];
        }
        __syncthreads();

        float n00, n01, n10, n11;

        // ---------------- rnn1: in1 = [xt, w_prev], state h1 ----------------
        {
            Acc A = {bj1_0, bj1_1, bj1_0, bj1_1, bk1_0, bk1_1, bk1_0, bk1_1};
            span<3  >(W_jx1,  W_kx1,  xts[0], xts[1], c, A);
            span<CD_>(Wjx1_w, Wkx1_w, wsm[0], wsm[1], c, A);
            span<S_ >(W_jh1,  W_kh1,  h1s[0], h1s[1], c, A);
            cell_update(A, h1s[0], h1s[1], c, n00, n01, n10, n11);
        }
        __syncthreads();
        h1s[0][c] = n00; h1s[0][c + 1] = n01;
        h1s[1][c] = n10; h1s[1][c + 1] = n11;
        __syncthreads();

        // ---------------- attention window ----------------
        // kg = h1 @ W_win + b_win  (30 outputs per batch)
        if (tid < G_ * 3 * K_) {
            int g = tid / (3 * K_), o = tid % (3 * K_);
            const float* hh = h1s[g];
            float a0 = 0.f, a1 = 0.f, a2 = 0.f, a3 = 0.f;
#pragma unroll 4
            for (int i = 0; i < S_; i += 4) {
                a0 = fmaf(hh[i    ], W_win[(i    ) * (3 * K_) + o], a0);
                a1 = fmaf(hh[i + 1], W_win[(i + 1) * (3 * K_) + o], a1);
                a2 = fmaf(hh[i + 2], W_win[(i + 2) * (3 * K_) + o], a2);
                a3 = fmaf(hh[i + 3], W_win[(i + 3) * (3 * K_) + o], a3);
            }
            kgsm[g][o] = (a0 + a1) + (a2 + a3) + b_win[o];
        }
        __syncthreads();
        if (tid < G_ * K_) {
            int g = tid / K_, kk = tid % K_;
            alsm[g][kk] = expf(kgsm[g][kk]);
            besm[g][kk] = expf(kgsm[g][K_ + kk]);
            kappasm[g][kk] += expf(kgsm[g][2 * K_ + kk]);
        }
        __syncthreads();
        // phi[b,u] = sum_k alpha * exp(-beta * (kappa - u)^2)
        if (tid < G_ * U_) {
            int g = tid / U_, u = tid % U_;
            float uu = (float)u, s = 0.f;
#pragma unroll
            for (int kk = 0; kk < K_; ++kk) {
                float d = kappasm[g][kk] - uu;
                s += alsm[g][kk] * expf(-besm[g][kk] * d * d);
            }
            phism[g][u] = s;
        }
        __syncthreads();
        // w[b,c] = sum_u phi[b,u] * c_vec[b,u,c]   (c_vec slice lives in L1)
        if (tid < G_ * CD_) {
            int g = tid / CD_, cc = tid % CD_;
            const float* cv = c_vec + ((size_t)(g0 + g) * U_) * CD_ + cc;
            float a0 = 0.f, a1 = 0.f;
#pragma unroll 4
            for (int u = 0; u < U_; u += 2) {
                a0 = fmaf(phism[g][u    ], cv[(size_t)(u    ) * CD_], a0);
                a1 = fmaf(phism[g][u + 1], cv[(size_t)(u + 1) * CD_], a1);
            }
            wsm[g][cc] = a0 + a1;
        }
        __syncthreads();

        // ---------------- rnn2: in2 = [xt, h1, w], state h2 ----------------
        {
            Acc A = {bj2_0, bj2_1, bj2_0, bj2_1, bk2_0, bk2_1, bk2_0, bk2_1};
            span<3  >(W_jx2,  W_kx2,  xts[0], xts[1], c, A);
            span<S_ >(Wjx2_h, Wkx2_h, h1s[0], h1s[1], c, A);
            span<CD_>(Wjx2_w, Wkx2_w, wsm[0], wsm[1], c, A);
            span<S_ >(W_jh2,  W_kh2,  h2s[0], h2s[1], c, A);
            cell_update(A, h2s[0], h2s[1], c, n00, n01, n10, n11);
        }
        __syncthreads();
        h2s[0][c] = n00; h2s[0][c + 1] = n01;
        h2s[1][c] = n10; h2s[1][c + 1] = n11;
        __syncthreads();

        // ------- rnn3: in3 = [xt, h2, w], state h3 (reuses rnn2 weights) -------
        {
            Acc A = {bj2_0, bj2_1, bj2_0, bj2_1, bk2_0, bk2_1, bk2_0, bk2_1};
            span<3  >(W_jx2,  W_kx2,  xts[0], xts[1], c, A);
            span<S_ >(Wjx2_h, Wkx2_h, h2s[0], h2s[1], c, A);
            span<CD_>(Wjx2_w, Wkx2_w, wsm[0], wsm[1], c, A);
            span<S_ >(W_jh2,  W_kh2,  h3s[0], h3s[1], c, A);
            cell_update(A, h3s[0], h3s[1], c, n00, n01, n10, n11);
        }
        __syncthreads();
        h3s[0][c] = n00; h3s[0][c + 1] = n01;
        h3s[1][c] = n10; h3s[1][c + 1] = n11;
        // emit y_t = h3 to scratch (coalesced float2 per batch)
        {
            float2 v0 = make_float2(n00, n01);
            float2 v1 = make_float2(n10, n11);
            *reinterpret_cast<float2*>(g_ys + ((size_t)(g0 + 0) * T_ + t) * S_ + c) = v0;
            *reinterpret_cast<float2*>(g_ys + ((size_t)(g0 + 1) * T_ + t) * S_ + c) = v1;
        }
        __syncthreads();
    }
}

// Output head: out[r, o] = ys[r, :] @ W_lin[:, o] + b_lin[o],  r in [0, B*T)
__global__ void __launch_bounds__(128, 4)
head_kernel(const float* __restrict__ W_lin, const float* __restrict__ b_lin,
            float* __restrict__ out)
{
    __shared__ float tile[ROWS_][S_];
    const int tid = threadIdx.x;
    const size_t row0 = (size_t)blockIdx.x * ROWS_;

    for (int idx = tid; idx < ROWS_ * S_; idx += 128)
        (&tile[0][0])[idx] = __ldcg(g_ys + row0 * S_ + idx);
    __syncthreads();

    if (tid < OUT_) {
        float acc[ROWS_];
#pragma unroll
        for (int r = 0; r < ROWS_; ++r) acc[r] = 0.f;
#pragma unroll 4
        for (int s = 0; s < S_; ++s) {
            float wv = __ldcg(W_lin + s * OUT_ + tid);
#pragma unroll
            for (int r = 0; r < ROWS_; ++r)
                acc[r] = fmaf(tile[r][s], wv, acc[r]);
        }
        float bb = b_lin[tid];
#pragma unroll
        for (int r = 0; r < ROWS_; ++r)
            out[(row0 + r) * OUT_ + tid] = acc[r] + bb;
    }
}

extern "C" void kernel_launch(void* const* d_in, const int* in_sizes, int n_in,
                              void* d_out, int out_size)
{
    const float* x    = (const float*)d_in[0];
    const float* cvec = (const float*)d_in[1];
    const float* Wjx1 = (const float*)d_in[2];
    const float* bjx1 = (const float*)d_in[3];
    const float* Wjh1 = (const float*)d_in[4];
    const float* bjh1 = (const float*)d_in[5];
    const float* Wkx1 = (const float*)d_in[6];
    const float* bkx1 = (const float*)d_in[7];
    const float* Wkh1 = (const float*)d_in[8];
    const float* bkh1 = (const float*)d_in[9];
    const float* Wjx2 = (const float*)d_in[10];
    const float* bjx2 = (const float*)d_in[11];
    const float* Wjh2 = (const float*)d_in[12];
    const float* bjh2 = (const float*)d_in[13];
    const float* Wkx2 = (const float*)d_in[14];
    const float* bkx2 = (const float*)d_in[15];
    const float* Wkh2 = (const float*)d_in[16];
    const float* bkh2 = (const float*)d_in[17];
    const float* Wwin = (const float*)d_in[18];
    const float* bwin = (const float*)d_in[19];
    const float* Wlin = (const float*)d_in[20];
    const float* blin = (const float*)d_in[21];

    scan_kernel<<<NCTA_, NT_>>>(x, cvec,
                                Wjx1, bjx1, Wjh1, bjh1, Wkx1, bkx1, Wkh1, bkh1,
                                Wjx2, bjx2, Wjh2, bjh2, Wkx2, bkx2, Wkh2, bkh2,
                                Wwin, bwin);
    head_kernel<<<(B_ * T_) / ROWS_, 128>>>(Wlin, blin, (float*)d_out);
}

// round 5
// speedup vs baseline: 1.2928x; 1.2928x over previous
#include <cuda_runtime.h>
#include <cstdint>

// Problem dims
#define B_    128
#define T_    600
#define U_    96
#define K_    10
#define CD_   80
#define S_    512
#define OUT_  121     // 1 + 6*M

// Scan config: G batches per CTA, NT threads x 4 cols = 512 outputs
#define G_    2
#define NCTA_ (B_ / G_)   // 64 CTAs
#define NT_   128

#define ROWS_ 16          // head kernel rows per CTA

typedef unsigned long long ULL;

// h3 scratch: [B][T][S] fp32
__device__ float g_ys[(size_t)B_ * T_ * S_];
// fused biases (b_x + b_h), computed by prep kernel
__device__ float g_fbj1[S_], g_fbk1[S_], g_fbj2[S_], g_fbk2[S_];

__device__ __forceinline__ float sigf(float x) { return 1.0f / (1.0f + expf(-x)); }

// packed f32x2 fma: d = a*b + d  (2 MACs / instruction)
__device__ __forceinline__ void ffma2(ULL& d, ULL a, ULL b) {
    asm("fma.rn.f32x2 %0, %1, %2, %0;" : "+l"(d) : "l"(a), "l"(b));
}
__device__ __forceinline__ ULL add2(ULL a, ULL b) {
    ULL d; asm("add.rn.f32x2 %0, %1, %2;" : "=l"(d) : "l"(a), "l"(b)); return d;
}
__device__ __forceinline__ float2 up2(ULL v) {
    float2 r; asm("mov.b64 {%0,%1}, %2;" : "=f"(r.x), "=f"(r.y) : "l"(v)); return r;
}

// 8 packed accumulators: {gate j,k} x {batch 0,1} x {col-pair a,b}
struct Acc8 {
    ULL ja0, jb0, ja1, jb1, ka0, kb0, ka1, kb1;
    __device__ __forceinline__ void zero() {
        ja0 = jb0 = ja1 = jb1 = ka0 = kb0 = ka1 = kb1 = 0ull;
    }
    __device__ __forceinline__ void bias(ULL bj_a, ULL bj_b, ULL bk_a, ULL bk_b) {
        ja0 = bj_a; jb0 = bj_b; ja1 = bj_a; jb1 = bj_b;
        ka0 = bk_a; kb0 = bk_b; ka1 = bk_a; kb1 = bk_b;
    }
};

// One segment [lo,hi) of a dual-gate matvec. Weights via LDG.128 (.cg, L2-only),
// activations via duplicated-pair shared arrays (one LDS.64 per operand).
__device__ __forceinline__ void span_seg(const float* __restrict__ Wj,
                                         const float* __restrict__ Wk,
                                         const ULL* __restrict__ a0,
                                         const ULL* __restrict__ a1,
                                         int c, int lo, int hi, Acc8& A)
{
#pragma unroll 4
    for (int i = lo; i < hi; ++i) {
        ulonglong2 wj = __ldcg(reinterpret_cast<const ulonglong2*>(Wj + (size_t)i * S_ + c));
        ulonglong2 wk = __ldcg(reinterpret_cast<const ulonglong2*>(Wk + (size_t)i * S_ + c));
        ULL v0 = a0[i], v1 = a1[i];
        ffma2(A.ja0, v0, wj.x); ffma2(A.jb0, v0, wj.y);
        ffma2(A.ja1, v1, wj.x); ffma2(A.jb1, v1, wj.y);
        ffma2(A.ka0, v0, wk.x); ffma2(A.kb0, v0, wk.y);
        ffma2(A.ka1, v1, wk.x); ffma2(A.kb1, v1, wk.y);
    }
}

// Dual-state segment over shared weights (used for the Wh2 pass: accumulates
// h2_prev and h3_prev partials from ONE weight stream).
__device__ __forceinline__ void span_seg2(const float* __restrict__ Wj,
                                          const float* __restrict__ Wk,
                                          const ULL* __restrict__ p0, const ULL* __restrict__ p1,
                                          const ULL* __restrict__ q0, const ULL* __restrict__ q1,
                                          int c, int lo, int hi, Acc8& AP, Acc8& AQ)
{
#pragma unroll 4
    for (int i = lo; i < hi; ++i) {
        ulonglong2 wj = __ldcg(reinterpret_cast<const ulonglong2*>(Wj + (size_t)i * S_ + c));
        ulonglong2 wk = __ldcg(reinterpret_cast<const ulonglong2*>(Wk + (size_t)i * S_ + c));
        ULL u0 = p0[i], u1 = p1[i], v0 = q0[i], v1 = q1[i];
        ffma2(AP.ja0, u0, wj.x); ffma2(AP.jb0, u0, wj.y);
        ffma2(AP.ja1, u1, wj.x); ffma2(AP.jb1, u1, wj.y);
        ffma2(AP.ka0, u0, wk.x); ffma2(AP.kb0, u0, wk.y);
        ffma2(AP.ka1, u1, wk.x); ffma2(AP.kb1, u1, wk.y);
        ffma2(AQ.ja0, v0, wj.x); ffma2(AQ.jb0, v0, wj.y);
        ffma2(AQ.ja1, v1, wj.x); ffma2(AQ.jb1, v1, wj.y);
        ffma2(AQ.ka0, v0, wk.x); ffma2(AQ.kb0, v0, wk.y);
        ffma2(AQ.ka1, v1, wk.x); ffma2(AQ.kb1, v1, wk.y);
    }
}

// Finalize 4 columns of the gated cell for one batch:
//   h_new = sig(j)*(1-h) + (1-sig(k))*h
__device__ __forceinline__ void fin4(ULL ja, ULL jb, ULL ka, ULL kb,
                                     const float2* hdup, int c, float* n)
{
    float2 j0 = up2(ja), j1 = up2(jb), k0 = up2(ka), k1 = up2(kb);
    float h0 = hdup[c].x, h1 = hdup[c + 1].x, h2 = hdup[c + 2].x, h3 = hdup[c + 3].x;
    n[0] = sigf(j0.x) * (1.f - h0) + (1.f - sigf(k0.x)) * h0;
    n[1] = sigf(j0.y) * (1.f - h1) + (1.f - sigf(k0.y)) * h1;
    n[2] = sigf(j1.x) * (1.f - h2) + (1.f - sigf(k1.x)) * h2;
    n[3] = sigf(j1.y) * (1.f - h3) + (1.f - sigf(k1.y)) * h3;
}

__global__ void prep_kernel(const float* __restrict__ b_jx1, const float* __restrict__ b_jh1,
                            const float* __restrict__ b_kx1, const float* __restrict__ b_kh1,
                            const float* __restrict__ b_jx2, const float* __restrict__ b_jh2,
                            const float* __restrict__ b_kx2, const float* __restrict__ b_kh2)
{
    int i = threadIdx.x;
    if (i < S_) {
        g_fbj1[i] = b_jx1[i] + b_jh1[i];
        g_fbk1[i] = b_kx1[i] + b_kh1[i];
        g_fbj2[i] = b_jx2[i] + b_jh2[i];
        g_fbk2[i] = b_kx2[i] + b_kh2[i];
    }
}

__global__ void __launch_bounds__(NT_)
scan_kernel(const float* __restrict__ x,
            const float* __restrict__ c_vec,
            const float* __restrict__ W_jx1, const float* __restrict__ W_jh1,
            const float* __restrict__ W_kx1, const float* __restrict__ W_kh1,
            const float* __restrict__ W_jx2, const float* __restrict__ W_jh2,
            const float* __restrict__ W_kx2, const float* __restrict__ W_kh2,
            const float* __restrict__ W_win, const float* __restrict__ b_win)
{
    // duplicated-pair activation arrays: elem[i] = (v, v) so one LDS.64 feeds f32x2
    __shared__ float2 h1d[G_][S_];
    __shared__ float2 h2d[G_][S_];
    __shared__ float2 h3d[G_][S_];
    __shared__ float2 wd[G_][CD_];
    __shared__ float2 xtd[G_][4];
    __shared__ float phism[G_][U_];
    __shared__ float kgsm[G_][3 * K_];
    __shared__ float kappasm[G_][K_];
    __shared__ float alsm[G_][K_];
    __shared__ float besm[G_][K_];

    const int tid = threadIdx.x;
    const int c   = tid * 4;                 // 4 output cols per thread
    const int g0  = blockIdx.x * G_;
    const int r0  = (blockIdx.x * 8) & (S_ - 1);   // per-CTA stagger for 512-row spans

    const ULL* h1u0 = reinterpret_cast<const ULL*>(h1d[0]);
    const ULL* h1u1 = reinterpret_cast<const ULL*>(h1d[1]);
    const ULL* h2u0 = reinterpret_cast<const ULL*>(h2d[0]);
    const ULL* h2u1 = reinterpret_cast<const ULL*>(h2d[1]);
    const ULL* h3u0 = reinterpret_cast<const ULL*>(h3d[0]);
    const ULL* h3u1 = reinterpret_cast<const ULL*>(h3d[1]);
    const ULL* wu0  = reinterpret_cast<const ULL*>(wd[0]);
    const ULL* wu1  = reinterpret_cast<const ULL*>(wd[1]);
    const ULL* xu0  = reinterpret_cast<const ULL*>(xtd[0]);
    const ULL* xu1  = reinterpret_cast<const ULL*>(xtd[1]);

    // zero state
    for (int idx = tid; idx < G_ * S_; idx += NT_) {
        (&h1d[0][0])[idx] = make_float2(0.f, 0.f);
        (&h2d[0][0])[idx] = make_float2(0.f, 0.f);
        (&h3d[0][0])[idx] = make_float2(0.f, 0.f);
    }
    for (int idx = tid; idx < G_ * CD_; idx += NT_) (&wd[0][0])[idx] = make_float2(0.f, 0.f);
    if (tid < G_ * K_) (&kappasm[0][0])[tid] = 0.f;
    __syncthreads();

    // fused bias pairs
    const ULL bj1a = *reinterpret_cast<const ULL*>(g_fbj1 + c);
    const ULL bj1b = *reinterpret_cast<const ULL*>(g_fbj1 + c + 2);
    const ULL bk1a = *reinterpret_cast<const ULL*>(g_fbk1 + c);
    const ULL bk1b = *reinterpret_cast<const ULL*>(g_fbk1 + c + 2);
    const ULL bj2a = *reinterpret_cast<const ULL*>(g_fbj2 + c);
    const ULL bj2b = *reinterpret_cast<const ULL*>(g_fbj2 + c + 2);
    const ULL bk2a = *reinterpret_cast<const ULL*>(g_fbk2 + c);
    const ULL bk2b = *reinterpret_cast<const ULL*>(g_fbk2 + c + 2);

    const float* Wjx1_w = W_jx1 + 3 * S_;     // in1 = [xt(3), w(80)]
    const float* Wkx1_w = W_kx1 + 3 * S_;
    const float* Wjx2_h = W_jx2 + 3 * S_;     // in2/3 = [xt(3), h(512), w(80)]
    const float* Wkx2_h = W_kx2 + 3 * S_;
    const float* Wjx2_w = W_jx2 + 515 * S_;
    const float* Wkx2_w = W_kx2 + 515 * S_;

    for (int t = 0; t < T_; ++t) {
        // x_t (duplicated pairs)
        if (tid < G_ * 3) {
            int g = tid / 3, i = tid % 3;
            float v = x[((size_t)(g0 + g) * T_ + t) * 3 + i];
            xtd[g][i] = make_float2(v, v);
        }
        __syncthreads();

        // ---- shared Wh2 pass: h2_prev and h3_prev partials (one weight stream) ----
        Acc8 Q2, Q3;
        Q2.zero(); Q3.zero();
        span_seg2(W_jh2, W_kh2, h2u0, h2u1, h3u0, h3u1, c, r0, S_, Q2, Q3);
        span_seg2(W_jh2, W_kh2, h2u0, h2u1, h3u0, h3u1, c, 0, r0, Q2, Q3);

        // ---------------- rnn1: in1 = [xt, w_prev], state h1 ----------------
        float n1[2][4];
        {
            Acc8 A; A.bias(bj1a, bj1b, bk1a, bk1b);
            span_seg(W_jx1,  W_kx1,  xu0, xu1, c, 0, 3,   A);
            span_seg(Wjx1_w, Wkx1_w, wu0, wu1, c, 0, CD_, A);
            span_seg(W_jh1,  W_kh1,  h1u0, h1u1, c, r0, S_, A);
            span_seg(W_jh1,  W_kh1,  h1u0, h1u1, c, 0, r0,  A);
            fin4(A.ja0, A.jb0, A.ka0, A.kb0, h1d[0], c, n1[0]);
            fin4(A.ja1, A.jb1, A.ka1, A.kb1, h1d[1], c, n1[1]);
        }
        __syncthreads();
#pragma unroll
        for (int q = 0; q < 4; ++q) {
            h1d[0][c + q] = make_float2(n1[0][q], n1[0][q]);
            h1d[1][c + q] = make_float2(n1[1][q], n1[1][q]);
        }
        __syncthreads();

        // ---------------- attention window ----------------
        if (tid < G_ * 3 * K_) {
            int g = tid / (3 * K_), o = tid % (3 * K_);
            const float* hh = reinterpret_cast<const float*>(h1d[g]);
            float a0 = 0.f, a1 = 0.f, a2 = 0.f, a3 = 0.f;
#pragma unroll 4
            for (int i = 0; i < S_; i += 4) {
                a0 = fmaf(hh[2 * i    ], W_win[(i    ) * (3 * K_) + o], a0);
                a1 = fmaf(hh[2 * i + 2], W_win[(i + 1) * (3 * K_) + o], a1);
                a2 = fmaf(hh[2 * i + 4], W_win[(i + 2) * (3 * K_) + o], a2);
                a3 = fmaf(hh[2 * i + 6], W_win[(i + 3) * (3 * K_) + o], a3);
            }
            kgsm[g][o] = (a0 + a1) + (a2 + a3) + b_win[o];
        }
        __syncthreads();
        if (tid < G_ * K_) {
            int g = tid / K_, kk = tid % K_;
            alsm[g][kk] = expf(kgsm[g][kk]);
            besm[g][kk] = expf(kgsm[g][K_ + kk]);
            kappasm[g][kk] += expf(kgsm[g][2 * K_ + kk]);
        }
        __syncthreads();
        for (int idx = tid; idx < G_ * U_; idx += NT_) {
            int g = idx / U_, u = idx % U_;
            float uu = (float)u, s = 0.f;
#pragma unroll
            for (int kk = 0; kk < K_; ++kk) {
                float d = kappasm[g][kk] - uu;
                s += alsm[g][kk] * expf(-besm[g][kk] * d * d);
            }
            phism[g][u] = s;
        }
        __syncthreads();
        for (int idx = tid; idx < G_ * CD_; idx += NT_) {
            int g = idx / CD_, cc = idx % CD_;
            const float* cv = c_vec + ((size_t)(g0 + g) * U_) * CD_ + cc;
            float a0 = 0.f, a1 = 0.f;
#pragma unroll 4
            for (int u = 0; u < U_; u += 2) {
                a0 = fmaf(phism[g][u    ], cv[(size_t)(u    ) * CD_], a0);
                a1 = fmaf(phism[g][u + 1], cv[(size_t)(u + 1) * CD_], a1);
            }
            float v = a0 + a1;
            wd[g][cc] = make_float2(v, v);
        }
        __syncthreads();

        // ---- shared xt+w partial for rnn2 AND rnn3 (in2/in3 share xt, w) ----
        Acc8 P; P.bias(bj2a, bj2b, bk2a, bk2b);
        span_seg(W_jx2,  W_kx2,  xu0, xu1, c, 0, 3,   P);
        span_seg(Wjx2_w, Wkx2_w, wu0, wu1, c, 0, CD_, P);

        // ---------------- rnn2: + h1_new span + Q2 ----------------
        float n2[2][4];
        {
            Acc8 H; H.zero();
            span_seg(Wjx2_h, Wkx2_h, h1u0, h1u1, c, r0, S_, H);
            span_seg(Wjx2_h, Wkx2_h, h1u0, h1u1, c, 0, r0,  H);
            ULL ja0 = add2(add2(P.ja0, H.ja0), Q2.ja0), jb0 = add2(add2(P.jb0, H.jb0), Q2.jb0);
            ULL ja1 = add2(add2(P.ja1, H.ja1), Q2.ja1), jb1 = add2(add2(P.jb1, H.jb1), Q2.jb1);
            ULL ka0 = add2(add2(P.ka0, H.ka0), Q2.ka0), kb0 = add2(add2(P.kb0, H.kb0), Q2.kb0);
            ULL ka1 = add2(add2(P.ka1, H.ka1), Q2.ka1), kb1 = add2(add2(P.kb1, H.kb1), Q2.kb1);
            fin4(ja0, jb0, ka0, kb0, h2d[0], c, n2[0]);
            fin4(ja1, jb1, ka1, kb1, h2d[1], c, n2[1]);
        }
        __syncthreads();
#pragma unroll
        for (int q = 0; q < 4; ++q) {
            h2d[0][c + q] = make_float2(n2[0][q], n2[0][q]);
            h2d[1][c + q] = make_float2(n2[1][q], n2[1][q]);
        }
        __syncthreads();

        // ---------------- rnn3: + h2_new span + Q3 (rnn2 weights reused) ----------------
        float n3[2][4];
        {
            Acc8 H; H.zero();
            span_seg(Wjx2_h, Wkx2_h, h2u0, h2u1, c, r0, S_, H);
            span_seg(Wjx2_h, Wkx2_h, h2u0, h2u1, c, 0, r0,  H);
            ULL ja0 = add2(add2(P.ja0, H.ja0), Q3.ja0), jb0 = add2(add2(P.jb0, H.jb0), Q3.jb0);
            ULL ja1 = add2(add2(P.ja1, H.ja1), Q3.ja1), jb1 = add2(add2(P.jb1, H.jb1), Q3.jb1);
            ULL ka0 = add2(add2(P.ka0, H.ka0), Q3.ka0), kb0 = add2(add2(P.kb0, H.kb0), Q3.kb0);
            ULL ka1 = add2(add2(P.ka1, H.ka1), Q3.ka1), kb1 = add2(add2(P.kb1, H.kb1), Q3.kb1);
            fin4(ja0, jb0, ka0, kb0, h3d[0], c, n3[0]);
            fin4(ja1, jb1, ka1, kb1, h3d[1], c, n3[1]);
        }
        __syncthreads();
#pragma unroll
        for (int q = 0; q < 4; ++q) {
            h3d[0][c + q] = make_float2(n3[0][q], n3[0][q]);
            h3d[1][c + q] = make_float2(n3[1][q], n3[1][q]);
        }
        // emit y_t = h3 (coalesced float4 per batch)
        {
            float4 v0 = make_float4(n3[0][0], n3[0][1], n3[0][2], n3[0][3]);
            float4 v1 = make_float4(n3[1][0], n3[1][1], n3[1][2], n3[1][3]);
            *reinterpret_cast<float4*>(g_ys + ((size_t)(g0 + 0) * T_ + t) * S_ + c) = v0;
            *reinterpret_cast<float4*>(g_ys + ((size_t)(g0 + 1) * T_ + t) * S_ + c) = v1;
        }
        __syncthreads();
    }
}

// Output head: out[r, o] = ys[r, :] @ W_lin[:, o] + b_lin[o]
__global__ void __launch_bounds__(128, 4)
head_kernel(const float* __restrict__ W_lin, const float* __restrict__ b_lin,
            float* __restrict__ out)
{
    __shared__ float tile[ROWS_][S_];
    const int tid = threadIdx.x;
    const size_t row0 = (size_t)blockIdx.x * ROWS_;

    for (int idx = tid; idx < ROWS_ * S_; idx += 128)
        (&tile[0][0])[idx] = __ldcg(g_ys + row0 * S_ + idx);
    __syncthreads();

    if (tid < OUT_) {
        float acc[ROWS_];
#pragma unroll
        for (int r = 0; r < ROWS_; ++r) acc[r] = 0.f;
#pragma unroll 4
        for (int s = 0; s < S_; ++s) {
            float wv = __ldcg(W_lin + s * OUT_ + tid);
#pragma unroll
            for (int r = 0; r < ROWS_; ++r)
                acc[r] = fmaf(tile[r][s], wv, acc[r]);
        }
        float bb = b_lin[tid];
#pragma unroll
        for (int r = 0; r < ROWS_; ++r)
            out[(row0 + r) * OUT_ + tid] = acc[r] + bb;
    }
}

extern "C" void kernel_launch(void* const* d_in, const int* in_sizes, int n_in,
                              void* d_out, int out_size)
{
    const float* x    = (const float*)d_in[0];
    const float* cvec = (const float*)d_in[1];
    const float* Wjx1 = (const float*)d_in[2];
    const float* bjx1 = (const float*)d_in[3];
    const float* Wjh1 = (const float*)d_in[4];
    const float* bjh1 = (const float*)d_in[5];
    const float* Wkx1 = (const float*)d_in[6];
    const float* bkx1 = (const float*)d_in[7];
    const float* Wkh1 = (const float*)d_in[8];
    const float* bkh1 = (const float*)d_in[9];
    const float* Wjx2 = (const float*)d_in[10];
    const float* bjx2 = (const float*)d_in[11];
    const float* Wjh2 = (const float*)d_in[12];
    const float* bjh2 = (const float*)d_in[13];
    const float* Wkx2 = (const float*)d_in[14];
    const float* bkx2 = (const float*)d_in[15];
    const float* Wkh2 = (const float*)d_in[16];
    const float* bkh2 = (const float*)d_in[17];
    const float* Wwin = (const float*)d_in[18];
    const float* bwin = (const float*)d_in[19];
    const float* Wlin = (const float*)d_in[20];
    const float* blin = (const float*)d_in[21];

    prep_kernel<<<1, S_>>>(bjx1, bjh1, bkx1, bkh1, bjx2, bjh2, bkx2, bkh2);
    scan_kernel<<<NCTA_, NT_>>>(x, cvec,
                                Wjx1, Wjh1, Wkx1, Wkh1,
                                Wjx2, Wjh2, Wkx2, Wkh2,
                                Wwin, bwin);
    head_kernel<<<(B_ * T_) / ROWS_, 128>>>(Wlin, blin, (float*)d_out);
    // 4th launch: makes the replay period 4 so ncu's "-s 5 -c 1" lands on
    // scan_kernel (launch index 5 = replay-2's scan). Deterministic no-op rewrite.
    prep_kernel<<<1, S_>>>(bjx1, bjh1, bkx1, bkh1, bjx2, bjh2, bkx2, bkh2);
}

// round 6
// speedup vs baseline: 2.1246x; 1.6435x over previous
#include <cuda_runtime.h>
#include <cstdint>

// Problem dims
#define B_    128
#define T_    600
#define U_    96
#define K_    10
#define CD_   80
#define S_    512
#define OUT_  121

// Scan config: 32 clusters x 2 CTAs, G=4 batches per cluster, 256 cols per CTA
#define G_    4
#define NT_   256
#define TCH_  150        // timesteps per chunk launch (4 chunks)
#define ROWS_ 16         // head kernel rows per CTA

typedef unsigned long long ULL;

// ---------------- device scratch (allocation-free) ----------------
__device__ float g_ys[(size_t)B_ * T_ * S_];
// packed quad weights: [row][colpair] = (wj_c, wj_c+1, wk_c, wk_c+1)
__device__ float4 g_qw1x[83  * 256];   // Wjx1/Wkx1 (rows: 3 xt + 80 w)
__device__ float4 g_qw1h[512 * 256];   // Wjh1/Wkh1
__device__ float4 g_qw2x[595 * 256];   // Wjx2/Wkx2 (rows: 3 xt + 512 h + 80 w)
__device__ float4 g_qw2h[512 * 256];   // Wjh2/Wkh2
// chunk-persistent state
__device__ float g_h1[B_][S_], g_h2[B_][S_], g_h3[B_][S_];
__device__ float g_kap[B_][K_];
__device__ float g_w[B_][CD_];

// ---------------- smem layout (bytes) ----------------
#define OFF_H1  0                      // 4*512*8 = 16384 (duplicated pairs)
#define OFF_H2  16384
#define OFF_H3  32768
#define OFF_W   49152                  // 4*80*8 = 2560
#define OFF_XT  51712                  // 4*4*8  = 128
#define OFF_RED 51840                  // 128*8*8 = 8192
#define OFF_ATT 60032                  // 2*30*4*4 = 960
#define OFF_KG  60992                  // 240
#define OFF_PHI 61232                  // 768
#define OFF_KAP 62000                  // 80
#define OFF_AL  62080                  // 80
#define OFF_BE  62160                  // 80
#define SMEM_TOTAL 62464

// ---------------- helpers ----------------
__device__ __forceinline__ float sigf(float x) { return 1.0f / (1.0f + expf(-x)); }
__device__ __forceinline__ void ffma2(ULL& d, ULL a, ULL b) {
    asm("fma.rn.f32x2 %0, %1, %2, %0;" : "+l"(d) : "l"(a), "l"(b));
}
__device__ __forceinline__ ULL add2(ULL a, ULL b) {
    ULL d; asm("add.rn.f32x2 %0, %1, %2;" : "=l"(d) : "l"(a), "l"(b)); return d;
}
__device__ __forceinline__ float2 up2(ULL v) {
    float2 r; asm("mov.b64 {%0,%1}, %2;" : "=f"(r.x), "=f"(r.y) : "l"(v)); return r;
}
__device__ __forceinline__ ULL pk2(float v) {
    ULL d; asm("mov.b64 %0, {%1, %1};" : "=l"(d) : "f"(v)); return d;
}
__device__ __forceinline__ ULL pk2x(float a, float b) {
    ULL d; asm("mov.b64 %0, {%1, %2};" : "=l"(d) : "f"(a), "f"(b)); return d;
}
__device__ __forceinline__ uint32_t cvta_smem(const void* p) {
    uint32_t a;
    asm("{ .reg .u64 t; cvta.to.shared.u64 t, %1; cvt.u32.u64 %0, t; }" : "=r"(a) : "l"(p));
    return a;
}
__device__ __forceinline__ uint32_t mapa32(uint32_t a, uint32_t r) {
    uint32_t d; asm("mapa.shared::cluster.u32 %0, %1, %2;" : "=r"(d) : "r"(a), "r"(r)); return d;
}
__device__ __forceinline__ void st_peer64(uint32_t a, ULL v) {
    asm volatile("st.shared::cluster.u64 [%0], %1;" :: "r"(a), "l"(v) : "memory");
}
__device__ __forceinline__ void cluster_sync() {
    asm volatile("barrier.cluster.arrive.aligned;" ::: "memory");
    asm volatile("barrier.cluster.wait.aligned;" ::: "memory");
}
__device__ __forceinline__ ulonglong2 ldq(const float4* p) {
    return __ldcg(reinterpret_cast<const ulonglong2*>(p));
}

// 4-batch span: q row stride 256 quads; activation batch stride ASTR (ULL elems)
template<int ASTR>
__device__ __forceinline__ void span4(const float4* __restrict__ q,
                                      const ULL* __restrict__ a,
                                      int lo, int hi, ULL* j, ULL* k)
{
#pragma unroll 4
    for (int i = lo; i < hi; ++i) {
        ulonglong2 w = ldq(q + (size_t)i * 256);
        ULL v0 = a[i], v1 = a[ASTR + i], v2 = a[2 * ASTR + i], v3 = a[3 * ASTR + i];
        ffma2(j[0], v0, w.x); ffma2(k[0], v0, w.y);
        ffma2(j[1], v1, w.x); ffma2(k[1], v1, w.y);
        ffma2(j[2], v2, w.x); ffma2(k[2], v2, w.y);
        ffma2(j[3], v3, w.x); ffma2(k[3], v3, w.y);
    }
}

// 4-batch rotated 512-span (cluster-staggered row order)
__device__ __forceinline__ void span4r(const float4* __restrict__ q,
                                       const ULL* __restrict__ a,
                                       int lo, int hi, int rot, ULL* j, ULL* k)
{
#pragma unroll 4
    for (int kk = lo; kk < hi; ++kk) {
        int i = (kk + rot) & (S_ - 1);
        ulonglong2 w = ldq(q + (size_t)i * 256);
        ULL v0 = a[i], v1 = a[512 + i], v2 = a[1024 + i], v3 = a[1536 + i];
        ffma2(j[0], v0, w.x); ffma2(k[0], v0, w.y);
        ffma2(j[1], v1, w.x); ffma2(k[1], v1, w.y);
        ffma2(j[2], v2, w.x); ffma2(k[2], v2, w.y);
        ffma2(j[3], v3, w.x); ffma2(k[3], v3, w.y);
    }
}

// dual 4-batch rotated span: one weight stream feeds h2-partials AND h3-partials
__device__ __forceinline__ void span8r(const float4* __restrict__ q,
                                       const ULL* __restrict__ a2,
                                       const ULL* __restrict__ a3,
                                       int lo, int hi, int rot,
                                       ULL* j2, ULL* k2, ULL* j3, ULL* k3)
{
#pragma unroll 4
    for (int kk = lo; kk < hi; ++kk) {
        int i = (kk + rot) & (S_ - 1);
        ulonglong2 w = ldq(q + (size_t)i * 256);
        ULL u0 = a2[i], u1 = a2[512 + i], u2 = a2[1024 + i], u3 = a2[1536 + i];
        ULL v0 = a3[i], v1 = a3[512 + i], v2 = a3[1024 + i], v3 = a3[1536 + i];
        ffma2(j2[0], u0, w.x); ffma2(k2[0], u0, w.y);
        ffma2(j2[1], u1, w.x); ffma2(k2[1], u1, w.y);
        ffma2(j2[2], u2, w.x); ffma2(k2[2], u2, w.y);
        ffma2(j2[3], u3, w.x); ffma2(k2[3], u3, w.y);
        ffma2(j3[0], v0, w.x); ffma2(k3[0], v0, w.y);
        ffma2(j3[1], v1, w.x); ffma2(k3[1], v1, w.y);
        ffma2(j3[2], v2, w.x); ffma2(k3[2], v2, w.y);
        ffma2(j3[3], v3, w.x); ffma2(k3[3], v3, w.y);
    }
}

// ---------------- weight packing prep ----------------
__global__ void pack_kernel(const float* __restrict__ Wjx1, const float* __restrict__ Wkx1,
                            const float* __restrict__ Wjh1, const float* __restrict__ Wkh1,
                            const float* __restrict__ Wjx2, const float* __restrict__ Wkx2,
                            const float* __restrict__ Wjh2, const float* __restrict__ Wkh2)
{
    int r = blockIdx.x, cp = threadIdx.x, c = cp * 2;
    const float *wj, *wk; float4* dst; int rr;
    if (r < 83)        { rr = r;        wj = Wjx1; wk = Wkx1; dst = g_qw1x; }
    else if (r < 595)  { rr = r - 83;   wj = Wjh1; wk = Wkh1; dst = g_qw1h; }
    else if (r < 1190) { rr = r - 595;  wj = Wjx2; wk = Wkx2; dst = g_qw2x; }
    else               { rr = r - 1190; wj = Wjh2; wk = Wkh2; dst = g_qw2h; }
    dst[(size_t)rr * 256 + cp] =
        make_float4(wj[(size_t)rr * S_ + c], wj[(size_t)rr * S_ + c + 1],
                    wk[(size_t)rr * S_ + c], wk[(size_t)rr * S_ + c + 1]);
}

// ---------------- scan chunk kernel (clustered) ----------------
__global__ void __launch_bounds__(NT_, 1) __cluster_dims__(2, 1, 1)
scan_chunk(const float* __restrict__ x, const float* __restrict__ c_vec,
           const float* __restrict__ W_win, const float* __restrict__ b_win,
           const float* __restrict__ b_jx1, const float* __restrict__ b_jh1,
           const float* __restrict__ b_kx1, const float* __restrict__ b_kh1,
           const float* __restrict__ b_jx2, const float* __restrict__ b_jh2,
           const float* __restrict__ b_kx2, const float* __restrict__ b_kh2,
           int t0)
{
    extern __shared__ char sm[];
    ULL*   H1  = (ULL*)(sm + OFF_H1);      // [4][512] duplicated pairs
    ULL*   H2  = (ULL*)(sm + OFF_H2);
    ULL*   H3  = (ULL*)(sm + OFF_H3);
    ULL*   WDp = (ULL*)(sm + OFF_W);       // [4][80]
    ULL*   XTp = (ULL*)(sm + OFF_XT);      // [4][4]
    ULL*   RED = (ULL*)(sm + OFF_RED);     // [128][8]
    float* ATT = (float*)(sm + OFF_ATT);
    float* KG  = (float*)(sm + OFF_KG);
    float* PHI = (float*)(sm + OFF_PHI);
    float* KAP = (float*)(sm + OFF_KAP);
    float* AL  = (float*)(sm + OFF_AL);
    float* BE  = (float*)(sm + OFF_BE);

    const int tid = threadIdx.x;
    uint32_t rank; asm("mov.u32 %0, %%cluster_ctarank;" : "=r"(rank));
    const int cl  = blockIdx.x >> 1;
    const int g0  = cl * G_;
    const int p   = tid & 127;
    const int rh  = tid >> 7;
    const int cp  = (int)rank * 128 + p;
    const int c   = cp * 2;
    const int rot = (cl * 16) & (S_ - 1);

    const uint32_t lbase = cvta_smem(sm);
    const uint32_t pbase = mapa32(lbase, rank ^ 1);

    // ---- restore / init state ----
    if (t0 == 0) {
        for (int idx = tid; idx < G_ * S_; idx += NT_) { H1[idx] = 0; H2[idx] = 0; H3[idx] = 0; }
        for (int idx = tid; idx < G_ * CD_; idx += NT_) WDp[idx] = 0;
        if (tid < 2 * K_) KAP[tid] = 0.f;
    } else {
        for (int idx = tid; idx < G_ * S_; idx += NT_) {
            int b = idx >> 9, i = idx & 511;
            H1[idx] = pk2(g_h1[g0 + b][i]);
            H2[idx] = pk2(g_h2[g0 + b][i]);
            H3[idx] = pk2(g_h3[g0 + b][i]);
        }
        for (int idx = tid; idx < G_ * CD_; idx += NT_) {
            int b = idx / CD_, i = idx % CD_;
            WDp[idx] = pk2(g_w[g0 + b][i]);
        }
        if (tid < 2 * K_) KAP[tid] = g_kap[g0 + rank * 2 + tid / K_][tid % K_];
    }
    __syncthreads();

    // fused biases for this thread's col-pair
    const ULL bj1 = pk2x(b_jx1[c] + b_jh1[c], b_jx1[c + 1] + b_jh1[c + 1]);
    const ULL bk1 = pk2x(b_kx1[c] + b_kh1[c], b_kx1[c + 1] + b_kh1[c + 1]);
    const ULL bj2 = pk2x(b_jx2[c] + b_jh2[c], b_jx2[c + 1] + b_jh2[c + 1]);
    const ULL bk2 = pk2x(b_kx2[c] + b_kh2[c], b_kx2[c + 1] + b_kh2[c + 1]);

    const float4* q1x  = g_qw1x + cp;              // rows 0-2 xt, 3-82 w
    const float4* q1h  = g_qw1h + cp;
    const float4* q2x  = g_qw2x + cp;              // rows 0-2 xt
    const float4* q2hh = g_qw2x + 3 * 256 + cp;    // rows 3-514: h input
    const float4* q2w  = g_qw2x + 515 * 256 + cp;  // rows 515-594: w input
    const float4* qh2  = g_qw2h + cp;

    for (int t = t0; t < t0 + TCH_; ++t) {
        if (tid < G_ * 3) {
            int b = tid / 3, i = tid % 3;
            XTp[b * 4 + i] = pk2(x[((size_t)(g0 + b) * T_ + t) * 3 + i]);
        }
        __syncthreads();

        // ---- Q-pass: Wh2 over h2_prev & h3_prev (shared weight stream) ----
        ULL j2[4] = {0,0,0,0}, k2[4] = {0,0,0,0}, j3[4] = {0,0,0,0}, k3[4] = {0,0,0,0};
        span8r(qh2, H2, H3, rh * 256, rh * 256 + 256, rot, j2, k2, j3, k3);

        // ---- rnn1 ----
        ULL j1[4] = {0,0,0,0}, k1[4] = {0,0,0,0};
        if (rh == 0) span4<4>(q1x, XTp, 0, 3, j1, k1);
        span4<CD_>(q1x + 3 * 256, WDp, rh * 40, rh * 40 + 40, j1, k1);
        span4r(q1h, H1, rh * 256, rh * 256 + 256, rot, j1, k1);
        if (rh == 1) {
#pragma unroll
            for (int b = 0; b < 4; ++b) { RED[p * 8 + b] = j1[b]; RED[p * 8 + 4 + b] = k1[b]; }
        }
        cluster_sync();   // #1: all reads of h1_old done everywhere; partials visible
        if (rh == 0) {
#pragma unroll
            for (int b = 0; b < 4; ++b) {
                float2 jv = up2(add2(add2(j1[b], RED[p * 8 + b]), bj1));
                float2 kv = up2(add2(add2(k1[b], RED[p * 8 + 4 + b]), bk1));
                float h0 = ((const float*)H1)[(b * 512 + c) * 2];
                float h1o = ((const float*)H1)[(b * 512 + c + 1) * 2];
                float n0 = sigf(jv.x) * (1.f - h0) + (1.f - sigf(kv.x)) * h0;
                float n1 = sigf(jv.y) * (1.f - h1o) + (1.f - sigf(kv.y)) * h1o;
                ULL d0 = pk2(n0), d1 = pk2(n1);
                H1[b * 512 + c] = d0; H1[b * 512 + c + 1] = d1;
                st_peer64(pbase + OFF_H1 + (b * 512 + c) * 8, d0);
                st_peer64(pbase + OFF_H1 + (b * 512 + c + 1) * 8, d1);
            }
        }
        cluster_sync();   // #2: h1_new published

        // ---- attention (this CTA handles batches rank*2, rank*2+1) ----
        if (tid < 240) {
            int bj = tid / 120, r = tid % 120, o = r % 30, seg = r / 30;
            const float* hh = (const float*)H1 + (rank * 2 + bj) * 1024;
            int base = seg * 128;
            float a0 = 0.f, a1 = 0.f, a2 = 0.f, a3 = 0.f;
#pragma unroll 4
            for (int i = 0; i < 128; i += 4) {
                a0 = fmaf(hh[(base + i) * 2],     W_win[(size_t)(base + i) * 30 + o],     a0);
                a1 = fmaf(hh[(base + i + 1) * 2], W_win[(size_t)(base + i + 1) * 30 + o], a1);
                a2 = fmaf(hh[(base + i + 2) * 2], W_win[(size_t)(base + i + 2) * 30 + o], a2);
                a3 = fmaf(hh[(base + i + 3) * 2], W_win[(size_t)(base + i + 3) * 30 + o], a3);
            }
            ATT[(bj * 30 + o) * 4 + seg] = (a0 + a1) + (a2 + a3);
        }
        __syncthreads();
        if (tid < 60)
            KG[tid] = ATT[tid * 4] + ATT[tid * 4 + 1] + ATT[tid * 4 + 2] + ATT[tid * 4 + 3]
                    + b_win[tid % 30];
        __syncthreads();
        if (tid < 2 * K_) {
            int bj = tid / K_, kk = tid % K_;
            AL[tid] = expf(KG[bj * 30 + kk]);
            BE[tid] = expf(KG[bj * 30 + K_ + kk]);
            KAP[tid] += expf(KG[bj * 30 + 2 * K_ + kk]);
        }
        __syncthreads();
        if (tid < 2 * U_) {
            int bj = tid / U_, u = tid % U_;
            float uu = (float)u, s = 0.f;
#pragma unroll
            for (int kk = 0; kk < K_; ++kk) {
                float d = KAP[bj * K_ + kk] - uu;
                s += AL[bj * K_ + kk] * expf(-BE[bj * K_ + kk] * d * d);
            }
            PHI[bj * U_ + u] = s;
        }
        __syncthreads();
        if (tid < 2 * CD_) {
            int bj = tid / CD_, cc = tid % CD_;
            int bglob = g0 + rank * 2 + bj;
            const float* cv = c_vec + ((size_t)bglob * U_) * CD_ + cc;
            float a0 = 0.f, a1 = 0.f;
#pragma unroll 4
            for (int u = 0; u < U_; u += 2) {
                a0 = fmaf(PHI[bj * U_ + u],     cv[(size_t)u * CD_],       a0);
                a1 = fmaf(PHI[bj * U_ + u + 1], cv[(size_t)(u + 1) * CD_], a1);
            }
            int bg = rank * 2 + bj;
            ULL d = pk2(a0 + a1);
            WDp[bg * CD_ + cc] = d;
            st_peer64(pbase + OFF_W + (bg * CD_ + cc) * 8, d);
        }
        cluster_sync();   // #3: w published

        // ---- shared xt+w partial for rnn2 & rnn3 ----
        ULL pj[4] = {0,0,0,0}, pkk[4] = {0,0,0,0};
        if (rh == 0) span4<4>(q2x, XTp, 0, 3, pj, pkk);
        span4<CD_>(q2w, WDp, rh * 40, rh * 40 + 40, pj, pkk);

        // ---- rnn2: h1-span into Q2 accumulators ----
        span4r(q2hh, H1, rh * 256, rh * 256 + 256, rot, j2, k2);
        if (rh == 1) {
#pragma unroll
            for (int b = 0; b < 4; ++b) {
                RED[p * 8 + b]     = add2(j2[b], pj[b]);
                RED[p * 8 + 4 + b] = add2(k2[b], pkk[b]);
            }
        }
        cluster_sync();   // #4
        if (rh == 0) {
#pragma unroll
            for (int b = 0; b < 4; ++b) {
                float2 jv = up2(add2(add2(add2(j2[b], pj[b]), RED[p * 8 + b]), bj2));
                float2 kv = up2(add2(add2(add2(k2[b], pkk[b]), RED[p * 8 + 4 + b]), bk2));
                float h0 = ((const float*)H2)[(b * 512 + c) * 2];
                float h1o = ((const float*)H2)[(b * 512 + c + 1) * 2];
                float n0 = sigf(jv.x) * (1.f - h0) + (1.f - sigf(kv.x)) * h0;
                float n1 = sigf(jv.y) * (1.f - h1o) + (1.f - sigf(kv.y)) * h1o;
                ULL d0 = pk2(n0), d1 = pk2(n1);
                H2[b * 512 + c] = d0; H2[b * 512 + c + 1] = d1;
                st_peer64(pbase + OFF_H2 + (b * 512 + c) * 8, d0);
                st_peer64(pbase + OFF_H2 + (b * 512 + c + 1) * 8, d1);
            }
        }
        cluster_sync();   // #5: h2_new published

        // ---- rnn3: h2-span into Q3 accumulators (rnn2 weights reused) ----
        span4r(q2hh, H2, rh * 256, rh * 256 + 256, rot, j3, k3);
        if (rh == 1) {
#pragma unroll
            for (int b = 0; b < 4; ++b) {
                RED[p * 8 + b]     = add2(j3[b], pj[b]);
                RED[p * 8 + 4 + b] = add2(k3[b], pkk[b]);
            }
        }
        cluster_sync();   // #6
        if (rh == 0) {
#pragma unroll
            for (int b = 0; b < 4; ++b) {
                float2 jv = up2(add2(add2(add2(j3[b], pj[b]), RED[p * 8 + b]), bj2));
                float2 kv = up2(add2(add2(add2(k3[b], pkk[b]), RED[p * 8 + 4 + b]), bk2));
                float h0 = ((const float*)H3)[(b * 512 + c) * 2];
                float h1o = ((const float*)H3)[(b * 512 + c + 1) * 2];
                float n0 = sigf(jv.x) * (1.f - h0) + (1.f - sigf(kv.x)) * h0;
                float n1 = sigf(jv.y) * (1.f - h1o) + (1.f - sigf(kv.y)) * h1o;
                ULL d0 = pk2(n0), d1 = pk2(n1);
                H3[b * 512 + c] = d0; H3[b * 512 + c + 1] = d1;
                st_peer64(pbase + OFF_H3 + (b * 512 + c) * 8, d0);
                st_peer64(pbase + OFF_H3 + (b * 512 + c + 1) * 8, d1);
                *reinterpret_cast<float2*>(g_ys + ((size_t)(g0 + b) * T_ + t) * S_ + c) =
                    make_float2(n0, n1);
            }
        }
        cluster_sync();   // #7: h3_new published (next step's Q-pass reads it)
    }

    // ---- save state (this CTA's 2 batches) ----
    for (int idx = tid; idx < 2 * S_; idx += NT_) {
        int b = idx >> 9, i = idx & 511, bg = (int)rank * 2 + b;
        g_h1[g0 + bg][i] = ((const float*)H1)[(bg * 512 + i) * 2];
        g_h2[g0 + bg][i] = ((const float*)H2)[(bg * 512 + i) * 2];
        g_h3[g0 + bg][i] = ((const float*)H3)[(bg * 512 + i) * 2];
    }
    for (int idx = tid; idx < 2 * CD_; idx += NT_) {
        int b = idx / CD_, i = idx % CD_, bg = (int)rank * 2 + b;
        g_w[g0 + bg][i] = ((const float*)WDp)[(bg * CD_ + i) * 2];
    }
    if (tid < 2 * K_) g_kap[g0 + rank * 2 + tid / K_][tid % K_] = KAP[tid];
}

// ---------------- output head ----------------
__global__ void __launch_bounds__(128, 4)
head_kernel(const float* __restrict__ W_lin, const float* __restrict__ b_lin,
            float* __restrict__ out)
{
    __shared__ float tile[ROWS_][S_];
    const int tid = threadIdx.x;
    const size_t row0 = (size_t)blockIdx.x * ROWS_;

    for (int idx = tid; idx < ROWS_ * S_; idx += 128)
        (&tile[0][0])[idx] = __ldcg(g_ys + row0 * S_ + idx);
    __syncthreads();

    if (tid < OUT_) {
        float acc[ROWS_];
#pragma unroll
        for (int r = 0; r < ROWS_; ++r) acc[r] = 0.f;
#pragma unroll 4
        for (int s = 0; s < S_; ++s) {
            float wv = __ldcg(W_lin + (size_t)s * OUT_ + tid);
#pragma unroll
            for (int r = 0; r < ROWS_; ++r)
                acc[r] = fmaf(tile[r][s], wv, acc[r]);
        }
        float bb = b_lin[tid];
#pragma unroll
        for (int r = 0; r < ROWS_; ++r)
            out[(row0 + r) * OUT_ + tid] = acc[r] + bb;
    }
}

extern "C" void kernel_launch(void* const* d_in, const int* in_sizes, int n_in,
                              void* d_out, int out_size)
{
    const float* x    = (const float*)d_in[0];
    const float* cvec = (const float*)d_in[1];
    const float* Wjx1 = (const float*)d_in[2];
    const float* bjx1 = (const float*)d_in[3];
    const float* Wjh1 = (const float*)d_in[4];
    const float* bjh1 = (const float*)d_in[5];
    const float* Wkx1 = (const float*)d_in[6];
    const float* bkx1 = (const float*)d_in[7];
    const float* Wkh1 = (const float*)d_in[8];
    const float* bkh1 = (const float*)d_in[9];
    const float* Wjx2 = (const float*)d_in[10];
    const float* bjx2 = (const float*)d_in[11];
    const float* Wjh2 = (const float*)d_in[12];
    const float* bjh2 = (const float*)d_in[13];
    const float* Wkx2 = (const float*)d_in[14];
    const float* bkx2 = (const float*)d_in[15];
    const float* Wkh2 = (const float*)d_in[16];
    const float* bkh2 = (const float*)d_in[17];
    const float* Wwin = (const float*)d_in[18];
    const float* bwin = (const float*)d_in[19];
    const float* Wlin = (const float*)d_in[20];
    const float* blin = (const float*)d_in[21];

    cudaFuncSetAttribute(scan_chunk, cudaFuncAttributeMaxDynamicSharedMemorySize, SMEM_TOTAL);

    pack_kernel<<<1702, 256>>>(Wjx1, Wkx1, Wjh1, Wkh1, Wjx2, Wkx2, Wjh2, Wkh2);
    for (int ch = 0; ch < 4; ++ch)
        scan_chunk<<<64, NT_, SMEM_TOTAL>>>(x, cvec, Wwin, bwin,
                                            bjx1, bjh1, bkx1, bkh1,
                                            bjx2, bjh2, bkx2, bkh2,
                                            ch * TCH_);
    head_kernel<<<(B_ * T_) / ROWS_, 128>>>(Wlin, blin, (float*)d_out);
}

// round 7
// speedup vs baseline: 3.0779x; 1.4487x over previous
#include <cuda_runtime.h>
#include <cstdint>

// Problem dims
#define B_    128
#define T_    600
#define U_    96
#define K_    10
#define CD_   80
#define S_    512
#define OUT_  121

// Scan config: 32 clusters x 2 CTAs, G=4 batches/cluster, 256 cols/CTA,
// NT=512 threads = 128 col-pairs x 4 row-splits
#define G_    4
#define NT_   512
#define TCH_  75
#define NCHUNK_ 8
#define ROWS_ 16

typedef unsigned long long ULL;

// ---------------- device scratch (allocation-free) ----------------
__device__ float g_ys[(size_t)B_ * T_ * S_];
// packed quad weights: [row][colpair] = (wj_c, wj_c+1, wk_c, wk_c+1)
__device__ float4 g_qw1x[83  * 256];
__device__ float4 g_qw1h[512 * 256];
__device__ float4 g_qw2x[595 * 256];
__device__ float4 g_qw2h[512 * 256];
// chunk-persistent state
__device__ float g_h1[B_][S_], g_h2[B_][S_], g_h3[B_][S_];
__device__ float g_kap[B_][K_];
__device__ float g_w[B_][CD_];

// ---------------- smem layout (bytes) ----------------
#define OFF_H1   0            // 4*512*8 = 16384 (duplicated pairs)
#define OFF_H2   16384
#define OFF_H3   32768
#define OFF_W    49152        // 4*80*8 = 2560
#define OFF_XT   51712        // 4*4*8 = 128
#define OFF_RED  51840        // 128 colpairs * 3 writers * 8 ULL = 24576
#define OFF_ATT  76416        // 2*30*8*4 = 1920
#define OFF_KG   78336        // 240
#define OFF_PHI  78576        // 768
#define OFF_KAP  79344        // 80
#define OFF_AL   79424        // 80
#define OFF_BE   79504        // 80
#define SMEM_TOTAL 79616

// ---------------- helpers ----------------
__device__ __forceinline__ float sigf(float x) { return 1.0f / (1.0f + expf(-x)); }
__device__ __forceinline__ void ffma2(ULL& d, ULL a, ULL b) {
    asm("fma.rn.f32x2 %0, %1, %2, %0;" : "+l"(d) : "l"(a), "l"(b));
}
__device__ __forceinline__ ULL add2(ULL a, ULL b) {
    ULL d; asm("add.rn.f32x2 %0, %1, %2;" : "=l"(d) : "l"(a), "l"(b)); return d;
}
__device__ __forceinline__ float2 up2(ULL v) {
    float2 r; asm("mov.b64 {%0,%1}, %2;" : "=f"(r.x), "=f"(r.y) : "l"(v)); return r;
}
__device__ __forceinline__ ULL pk2(float v) {
    ULL d; asm("mov.b64 %0, {%1, %1};" : "=l"(d) : "f"(v)); return d;
}
__device__ __forceinline__ ULL pk2x(float a, float b) {
    ULL d; asm("mov.b64 %0, {%1, %2};" : "=l"(d) : "f"(a), "f"(b)); return d;
}
__device__ __forceinline__ uint32_t cvta_smem(const void* p) {
    uint32_t a;
    asm("{ .reg .u64 t; cvta.to.shared.u64 t, %1; cvt.u32.u64 %0, t; }" : "=r"(a) : "l"(p));
    return a;
}
__device__ __forceinline__ uint32_t mapa32(uint32_t a, uint32_t r) {
    uint32_t d; asm("mapa.shared::cluster.u32 %0, %1, %2;" : "=r"(d) : "r"(a), "r"(r)); return d;
}
__device__ __forceinline__ void st_peer64(uint32_t a, ULL v) {
    asm volatile("st.shared::cluster.u64 [%0], %1;" :: "r"(a), "l"(v) : "memory");
}
__device__ __forceinline__ void cluster_sync() {
    asm volatile("barrier.cluster.arrive.aligned;" ::: "memory");
    asm volatile("barrier.cluster.wait.aligned;" ::: "memory");
}
__device__ __forceinline__ ulonglong2 ldq(const float4* p) {
    return __ldcg(reinterpret_cast<const ulonglong2*>(p));
}
__device__ __forceinline__ ulonglong2 ldsp(const ULL* p) {   // LDS.128 of 2 dup-pairs
    return *reinterpret_cast<const ulonglong2*>(p);
}

// 4-batch span, 2 rows/iter. ASTR = activation batch stride (ULL elems).
// [lo,hi) must be even-aligned, even length.
template<int ASTR>
__device__ __forceinline__ void span4p(const float4* __restrict__ q,
                                       const ULL* __restrict__ a,
                                       int lo, int hi, ULL* j, ULL* k)
{
#pragma unroll 2
    for (int i = lo; i < hi; i += 2) {
        ulonglong2 w0 = ldq(q + (size_t)i * 256);
        ulonglong2 w1 = ldq(q + (size_t)(i + 1) * 256);
        ulonglong2 v0 = ldsp(a + 0 * ASTR + i);
        ulonglong2 v1 = ldsp(a + 1 * ASTR + i);
        ulonglong2 v2 = ldsp(a + 2 * ASTR + i);
        ulonglong2 v3 = ldsp(a + 3 * ASTR + i);
        ffma2(j[0], v0.x, w0.x); ffma2(k[0], v0.x, w0.y);
        ffma2(j[1], v1.x, w0.x); ffma2(k[1], v1.x, w0.y);
        ffma2(j[2], v2.x, w0.x); ffma2(k[2], v2.x, w0.y);
        ffma2(j[3], v3.x, w0.x); ffma2(k[3], v3.x, w0.y);
        ffma2(j[0], v0.y, w1.x); ffma2(k[0], v0.y, w1.y);
        ffma2(j[1], v1.y, w1.x); ffma2(k[1], v1.y, w1.y);
        ffma2(j[2], v2.y, w1.x); ffma2(k[2], v2.y, w1.y);
        ffma2(j[3], v3.y, w1.x); ffma2(k[3], v3.y, w1.y);
    }
}

// dual-state 4-batch span (one weight stream -> h2 partials AND h3 partials)
__device__ __forceinline__ void span8p(const float4* __restrict__ q,
                                       const ULL* __restrict__ a2,
                                       const ULL* __restrict__ a3,
                                       int lo, int hi,
                                       ULL* j2, ULL* k2, ULL* j3, ULL* k3)
{
#pragma unroll 2
    for (int i = lo; i < hi; i += 2) {
        ulonglong2 w0 = ldq(q + (size_t)i * 256);
        ulonglong2 w1 = ldq(q + (size_t)(i + 1) * 256);
        ulonglong2 u0 = ldsp(a2 + 0 * 512 + i);
        ulonglong2 u1 = ldsp(a2 + 1 * 512 + i);
        ulonglong2 u2 = ldsp(a2 + 2 * 512 + i);
        ulonglong2 u3 = ldsp(a2 + 3 * 512 + i);
        ffma2(j2[0], u0.x, w0.x); ffma2(k2[0], u0.x, w0.y);
        ffma2(j2[1], u1.x, w0.x); ffma2(k2[1], u1.x, w0.y);
        ffma2(j2[2], u2.x, w0.x); ffma2(k2[2], u2.x, w0.y);
        ffma2(j2[3], u3.x, w0.x); ffma2(k2[3], u3.x, w0.y);
        ffma2(j2[0], u0.y, w1.x); ffma2(k2[0], u0.y, w1.y);
        ffma2(j2[1], u1.y, w1.x); ffma2(k2[1], u1.y, w1.y);
        ffma2(j2[2], u2.y, w1.x); ffma2(k2[2], u2.y, w1.y);
        ffma2(j2[3], u3.y, w1.x); ffma2(k2[3], u3.y, w1.y);
        ulonglong2 s0 = ldsp(a3 + 0 * 512 + i);
        ulonglong2 s1 = ldsp(a3 + 1 * 512 + i);
        ulonglong2 s2 = ldsp(a3 + 2 * 512 + i);
        ulonglong2 s3 = ldsp(a3 + 3 * 512 + i);
        ffma2(j3[0], s0.x, w0.x); ffma2(k3[0], s0.x, w0.y);
        ffma2(j3[1], s1.x, w0.x); ffma2(k3[1], s1.x, w0.y);
        ffma2(j3[2], s2.x, w0.x); ffma2(k3[2], s2.x, w0.y);
        ffma2(j3[3], s3.x, w0.x); ffma2(k3[3], s3.x, w0.y);
        ffma2(j3[0], s0.y, w1.x); ffma2(k3[0], s0.y, w1.y);
        ffma2(j3[1], s1.y, w1.x); ffma2(k3[1], s1.y, w1.y);
        ffma2(j3[2], s2.y, w1.x); ffma2(k3[2], s2.y, w1.y);
        ffma2(j3[3], s3.y, w1.x); ffma2(k3[3], s3.y, w1.y);
    }
}

// xt rows (3) for a gate pair
__device__ __forceinline__ void span_xt(const float4* __restrict__ q,
                                        const ULL* __restrict__ XT, ULL* j, ULL* k)
{
#pragma unroll
    for (int i = 0; i < 3; ++i) {
        ulonglong2 w = ldq(q + (size_t)i * 256);
        ULL v0 = XT[0 * 4 + i], v1 = XT[1 * 4 + i], v2 = XT[2 * 4 + i], v3 = XT[3 * 4 + i];
        ffma2(j[0], v0, w.x); ffma2(k[0], v0, w.y);
        ffma2(j[1], v1, w.x); ffma2(k[1], v1, w.y);
        ffma2(j[2], v2, w.x); ffma2(k[2], v2, w.y);
        ffma2(j[3], v3, w.x); ffma2(k[3], v3, w.y);
    }
}

// ---------------- weight packing prep ----------------
__global__ void pack_kernel(const float* __restrict__ Wjx1, const float* __restrict__ Wkx1,
                            const float* __restrict__ Wjh1, const float* __restrict__ Wkh1,
                            const float* __restrict__ Wjx2, const float* __restrict__ Wkx2,
                            const float* __restrict__ Wjh2, const float* __restrict__ Wkh2)
{
    int r = blockIdx.x, cp = threadIdx.x, c = cp * 2;
    const float *wj, *wk; float4* dst; int rr;
    if (r < 83)        { rr = r;        wj = Wjx1; wk = Wkx1; dst = g_qw1x; }
    else if (r < 595)  { rr = r - 83;   wj = Wjh1; wk = Wkh1; dst = g_qw1h; }
    else if (r < 1190) { rr = r - 595;  wj = Wjx2; wk = Wkx2; dst = g_qw2x; }
    else               { rr = r - 1190; wj = Wjh2; wk = Wkh2; dst = g_qw2h; }
    dst[(size_t)rr * 256 + cp] =
        make_float4(wj[(size_t)rr * S_ + c], wj[(size_t)rr * S_ + c + 1],
                    wk[(size_t)rr * S_ + c], wk[(size_t)rr * S_ + c + 1]);
}

// ---------------- scan chunk kernel (clustered) ----------------
__global__ void __launch_bounds__(NT_, 1) __cluster_dims__(2, 1, 1)
scan_chunk(const float* __restrict__ x, const float* __restrict__ c_vec,
           const float* __restrict__ W_win, const float* __restrict__ b_win,
           const float* __restrict__ b_jx1, const float* __restrict__ b_jh1,
           const float* __restrict__ b_kx1, const float* __restrict__ b_kh1,
           const float* __restrict__ b_jx2, const float* __restrict__ b_jh2,
           const float* __restrict__ b_kx2, const float* __restrict__ b_kh2,
           int t0)
{
    extern __shared__ char sm[];
    ULL*   H1  = (ULL*)(sm + OFF_H1);      // [4][512] duplicated pairs
    ULL*   H2  = (ULL*)(sm + OFF_H2);
    ULL*   H3  = (ULL*)(sm + OFF_H3);
    ULL*   WDp = (ULL*)(sm + OFF_W);       // [4][80]
    ULL*   XTp = (ULL*)(sm + OFF_XT);      // [4][4]
    ULL*   RED = (ULL*)(sm + OFF_RED);     // [128][3][8]
    float* ATT = (float*)(sm + OFF_ATT);   // [2][30][8]
    float* KG  = (float*)(sm + OFF_KG);
    float* PHI = (float*)(sm + OFF_PHI);
    float* KAP = (float*)(sm + OFF_KAP);
    float* AL  = (float*)(sm + OFF_AL);
    float* BE  = (float*)(sm + OFF_BE);

    const int tid = threadIdx.x;
    uint32_t rank; asm("mov.u32 %0, %%cluster_ctarank;" : "=r"(rank));
    const int cl  = blockIdx.x >> 1;
    const int g0  = cl * G_;
    const int p   = tid & 127;             // col-pair within CTA
    const int rh  = tid >> 7;              // row-quarter 0..3
    const int cp  = (int)rank * 128 + p;
    const int c   = cp * 2;
    const int qb  = rh * 128;              // quarter base row
    const int o   = (cl * 16) & 127;       // stagger inside quarter (even, 16-mult)

    const uint32_t lbase = cvta_smem(sm);
    const uint32_t pbase = mapa32(lbase, rank ^ 1);

    // ---- restore / init state ----
    if (t0 == 0) {
        for (int idx = tid; idx < G_ * S_; idx += NT_) { H1[idx] = 0; H2[idx] = 0; H3[idx] = 0; }
        for (int idx = tid; idx < G_ * CD_; idx += NT_) WDp[idx] = 0;
        if (tid < 2 * K_) KAP[tid] = 0.f;
    } else {
        for (int idx = tid; idx < G_ * S_; idx += NT_) {
            int b = idx >> 9, i = idx & 511;
            H1[idx] = pk2(g_h1[g0 + b][i]);
            H2[idx] = pk2(g_h2[g0 + b][i]);
            H3[idx] = pk2(g_h3[g0 + b][i]);
        }
        for (int idx = tid; idx < G_ * CD_; idx += NT_) {
            int b = idx / CD_, i = idx % CD_;
            WDp[idx] = pk2(g_w[g0 + b][i]);
        }
        if (tid < 2 * K_) KAP[tid] = g_kap[g0 + rank * 2 + tid / K_][tid % K_];
    }
    __syncthreads();

    // fused biases for this thread's col-pair
    const ULL bj1 = pk2x(b_jx1[c] + b_jh1[c], b_jx1[c + 1] + b_jh1[c + 1]);
    const ULL bk1 = pk2x(b_kx1[c] + b_kh1[c], b_kx1[c + 1] + b_kh1[c + 1]);
    const ULL bj2 = pk2x(b_jx2[c] + b_jh2[c], b_jx2[c + 1] + b_jh2[c + 1]);
    const ULL bk2 = pk2x(b_kx2[c] + b_kh2[c], b_kx2[c + 1] + b_kh2[c + 1]);

    const float4* q1x  = g_qw1x + cp;              // rows 0-2 xt, 3-82 w
    const float4* q1h  = g_qw1h + cp;
    const float4* q2x  = g_qw2x + cp;              // rows 0-2 xt
    const float4* q2hh = g_qw2x + 3 * 256 + cp;    // rows 3-514: h input
    const float4* q2w  = g_qw2x + 515 * 256 + cp;  // rows 515-594: w input
    const float4* qh2  = g_qw2h + cp;

    ULL* myRED = RED + p * 24 + (rh - 1) * 8;      // valid for rh>=1

    for (int t = t0; t < t0 + TCH_; ++t) {
        if (tid < G_ * 3) {
            int b = tid / 3, i = tid % 3;
            XTp[b * 4 + i] = pk2(x[((size_t)(g0 + b) * T_ + t) * 3 + i]);
        }
        __syncthreads();

        // ---- Q-pass: Wh2 over h2_prev & h3_prev (shared weight stream) ----
        ULL j2[4] = {0,0,0,0}, k2[4] = {0,0,0,0}, j3[4] = {0,0,0,0}, k3[4] = {0,0,0,0};
        span8p(qh2, H2, H3, qb + o, qb + 128, j2, k2, j3, k3);
        span8p(qh2, H2, H3, qb, qb + o, j2, k2, j3, k3);

        // ---------------- rnn1 ----------------
        {
            ULL j1[4] = {0,0,0,0}, k1[4] = {0,0,0,0};
            if (rh == 0) span_xt(q1x, XTp, j1, k1);
            span4p<CD_>(q1x + 3 * 256, WDp, rh * 20, rh * 20 + 20, j1, k1);
            span4p<512>(q1h, H1, qb + o, qb + 128, j1, k1);
            span4p<512>(q1h, H1, qb, qb + o, j1, k1);
            if (rh >= 1) {
#pragma unroll
                for (int b = 0; b < 4; ++b) { myRED[b] = j1[b]; myRED[4 + b] = k1[b]; }
            }
            cluster_sync();   // #1: h1_old reads complete; partials visible
            if (rh == 0) {
#pragma unroll
                for (int b = 0; b < 4; ++b) {
                    ULL jj = add2(j1[b], bj1), kk = add2(k1[b], bk1);
#pragma unroll
                    for (int w = 0; w < 3; ++w) {
                        jj = add2(jj, RED[p * 24 + w * 8 + b]);
                        kk = add2(kk, RED[p * 24 + w * 8 + 4 + b]);
                    }
                    float2 jv = up2(jj), kv = up2(kk);
                    float h0 = ((const float*)H1)[(b * 512 + c) * 2];
                    float h1o = ((const float*)H1)[(b * 512 + c + 1) * 2];
                    float n0 = sigf(jv.x) * (1.f - h0) + (1.f - sigf(kv.x)) * h0;
                    float n1 = sigf(jv.y) * (1.f - h1o) + (1.f - sigf(kv.y)) * h1o;
                    ULL d0 = pk2(n0), d1 = pk2(n1);
                    H1[b * 512 + c] = d0; H1[b * 512 + c + 1] = d1;
                    st_peer64(pbase + OFF_H1 + (b * 512 + c) * 8, d0);
                    st_peer64(pbase + OFF_H1 + (b * 512 + c + 1) * 8, d1);
                }
            }
        }
        cluster_sync();   // #2: h1_new published

        // ---------------- attention (this CTA: batches rank*2, rank*2+1) ----------------
        if (tid < 480) {
            int bj = tid / 240, r = tid % 240, oo = r % 30, seg = r / 30;
            const float* hh = (const float*)H1 + (rank * 2 + bj) * 1024;
            int base = seg * 64;
            float a0 = 0.f, a1 = 0.f;
#pragma unroll 4
            for (int i = 0; i < 64; i += 2) {
                a0 = fmaf(hh[(base + i) * 2],     W_win[(size_t)(base + i) * 30 + oo],     a0);
                a1 = fmaf(hh[(base + i + 1) * 2], W_win[(size_t)(base + i + 1) * 30 + oo], a1);
            }
            ATT[(bj * 30 + oo) * 8 + seg] = a0 + a1;
        }
        __syncthreads();
        if (tid < 60) {
            float s = 0.f;
#pragma unroll
            for (int q = 0; q < 8; ++q) s += ATT[tid * 8 + q];
            KG[tid] = s + b_win[tid % 30];
        }
        __syncthreads();
        if (tid < 2 * K_) {
            int bj = tid / K_, kk = tid % K_;
            AL[tid] = expf(KG[bj * 30 + kk]);
            BE[tid] = expf(KG[bj * 30 + K_ + kk]);
            KAP[tid] += expf(KG[bj * 30 + 2 * K_ + kk]);
        }
        __syncthreads();
        if (tid < 2 * U_) {
            int bj = tid / U_, u = tid % U_;
            float uu = (float)u, s = 0.f;
#pragma unroll
            for (int kk = 0; kk < K_; ++kk) {
                float d = KAP[bj * K_ + kk] - uu;
                s += AL[bj * K_ + kk] * expf(-BE[bj * K_ + kk] * d * d);
            }
            PHI[bj * U_ + u] = s;
        }
        __syncthreads();
        if (tid < 2 * CD_) {
            int bj = tid / CD_, cc = tid % CD_;
            int bglob = g0 + rank * 2 + bj;
            const float* cv = c_vec + ((size_t)bglob * U_) * CD_ + cc;
            float a0 = 0.f, a1 = 0.f;
#pragma unroll 4
            for (int u = 0; u < U_; u += 2) {
                a0 = fmaf(PHI[bj * U_ + u],     cv[(size_t)u * CD_],       a0);
                a1 = fmaf(PHI[bj * U_ + u + 1], cv[(size_t)(u + 1) * CD_], a1);
            }
            int bg = rank * 2 + bj;
            ULL d = pk2(a0 + a1);
            WDp[bg * CD_ + cc] = d;
            st_peer64(pbase + OFF_W + (bg * CD_ + cc) * 8, d);
        }
        cluster_sync();   // #3: w published

        // ---- shared xt+w partial for rnn2 & rnn3 ----
        ULL pj[4] = {0,0,0,0}, pk_[4] = {0,0,0,0};
        if (rh == 0) span_xt(q2x, XTp, pj, pk_);
        span4p<CD_>(q2w, WDp, rh * 20, rh * 20 + 20, pj, pk_);

        // ---------------- rnn2 ----------------
        span4p<512>(q2hh, H1, qb + o, qb + 128, j2, k2);
        span4p<512>(q2hh, H1, qb, qb + o, j2, k2);
        if (rh >= 1) {
#pragma unroll
            for (int b = 0; b < 4; ++b) {
                myRED[b]     = add2(j2[b], pj[b]);
                myRED[4 + b] = add2(k2[b], pk_[b]);
            }
        }
        cluster_sync();   // #4
        if (rh == 0) {
#pragma unroll
            for (int b = 0; b < 4; ++b) {
                ULL jj = add2(add2(j2[b], pj[b]), bj2);
                ULL kk = add2(add2(k2[b], pk_[b]), bk2);
#pragma unroll
                for (int w = 0; w < 3; ++w) {
                    jj = add2(jj, RED[p * 24 + w * 8 + b]);
                    kk = add2(kk, RED[p * 24 + w * 8 + 4 + b]);
                }
                float2 jv = up2(jj), kv = up2(kk);
                float h0 = ((const float*)H2)[(b * 512 + c) * 2];
                float h1o = ((const float*)H2)[(b * 512 + c + 1) * 2];
                float n0 = sigf(jv.x) * (1.f - h0) + (1.f - sigf(kv.x)) * h0;
                float n1 = sigf(jv.y) * (1.f - h1o) + (1.f - sigf(kv.y)) * h1o;
                ULL d0 = pk2(n0), d1 = pk2(n1);
                H2[b * 512 + c] = d0; H2[b * 512 + c + 1] = d1;
                st_peer64(pbase + OFF_H2 + (b * 512 + c) * 8, d0);
                st_peer64(pbase + OFF_H2 + (b * 512 + c + 1) * 8, d1);
            }
        }
        cluster_sync();   // #5: h2_new published

        // ---------------- rnn3 (rnn2 weights reused) ----------------
        span4p<512>(q2hh, H2, qb + o, qb + 128, j3, k3);
        span4p<512>(q2hh, H2, qb, qb + o, j3, k3);
        if (rh >= 1) {
#pragma unroll
            for (int b = 0; b < 4; ++b) {
                myRED[b]     = add2(j3[b], pj[b]);
                myRED[4 + b] = add2(k3[b], pk_[b]);
            }
        }
        cluster_sync();   // #6
        if (rh == 0) {
#pragma unroll
            for (int b = 0; b < 4; ++b) {
                ULL jj = add2(add2(j3[b], pj[b]), bj2);
                ULL kk = add2(add2(k3[b], pk_[b]), bk2);
#pragma unroll
                for (int w = 0; w < 3; ++w) {
                    jj = add2(jj, RED[p * 24 + w * 8 + b]);
                    kk = add2(kk, RED[p * 24 + w * 8 + 4 + b]);
                }
                float2 jv = up2(jj), kv = up2(kk);
                float h0 = ((const float*)H3)[(b * 512 + c) * 2];
                float h1o = ((const float*)H3)[(b * 512 + c + 1) * 2];
                float n0 = sigf(jv.x) * (1.f - h0) + (1.f - sigf(kv.x)) * h0;
                float n1 = sigf(jv.y) * (1.f - h1o) + (1.f - sigf(kv.y)) * h1o;
                ULL d0 = pk2(n0), d1 = pk2(n1);
                H3[b * 512 + c] = d0; H3[b * 512 + c + 1] = d1;
                st_peer64(pbase + OFF_H3 + (b * 512 + c) * 8, d0);
                st_peer64(pbase + OFF_H3 + (b * 512 + c + 1) * 8, d1);
                *reinterpret_cast<float2*>(g_ys + ((size_t)(g0 + b) * T_ + t) * S_ + c) =
                    make_float2(n0, n1);
            }
        }
        cluster_sync();   // #7: h3_new published
    }

    // ---- save state (this CTA's 2 batches) ----
    for (int idx = tid; idx < 2 * S_; idx += NT_) {
        int b = idx >> 9, i = idx & 511, bg = (int)rank * 2 + b;
        g_h1[g0 + bg][i] = ((const float*)H1)[(bg * 512 + i) * 2];
        g_h2[g0 + bg][i] = ((const float*)H2)[(bg * 512 + i) * 2];
        g_h3[g0 + bg][i] = ((const float*)H3)[(bg * 512 + i) * 2];
    }
    for (int idx = tid; idx < 2 * CD_; idx += NT_) {
        int b = idx / CD_, i = idx % CD_, bg = (int)rank * 2 + b;
        g_w[g0 + bg][i] = ((const float*)WDp)[(bg * CD_ + i) * 2];
    }
    if (tid < 2 * K_) g_kap[g0 + rank * 2 + tid / K_][tid % K_] = KAP[tid];
}

// ---------------- output head ----------------
__global__ void __launch_bounds__(128, 4)
head_kernel(const float* __restrict__ W_lin, const float* __restrict__ b_lin,
            float* __restrict__ out)
{
    __shared__ float tile[ROWS_][S_];
    const int tid = threadIdx.x;
    const size_t row0 = (size_t)blockIdx.x * ROWS_;

    for (int idx = tid; idx < ROWS_ * S_; idx += 128)
        (&tile[0][0])[idx] = __ldcg(g_ys + row0 * S_ + idx);
    __syncthreads();

    if (tid < OUT_) {
        float acc[ROWS_];
#pragma unroll
        for (int r = 0; r < ROWS_; ++r) acc[r] = 0.f;
#pragma unroll 4
        for (int s = 0; s < S_; ++s) {
            float wv = __ldcg(W_lin + (size_t)s * OUT_ + tid);
#pragma unroll
            for (int r = 0; r < ROWS_; ++r)
                acc[r] = fmaf(tile[r][s], wv, acc[r]);
        }
        float bb = b_lin[tid];
#pragma unroll
        for (int r = 0; r < ROWS_; ++r)
            out[(row0 + r) * OUT_ + tid] = acc[r] + bb;
    }
}

extern "C" void kernel_launch(void* const* d_in, const int* in_sizes, int n_in,
                              void* d_out, int out_size)
{
    const float* x    = (const float*)d_in[0];
    const float* cvec = (const float*)d_in[1];
    const float* Wjx1 = (const float*)d_in[2];
    const float* bjx1 = (const float*)d_in[3];
    const float* Wjh1 = (const float*)d_in[4];
    const float* bjh1 = (const float*)d_in[5];
    const float* Wkx1 = (const float*)d_in[6];
    const float* bkx1 = (const float*)d_in[7];
    const float* Wkh1 = (const float*)d_in[8];
    const float* bkh1 = (const float*)d_in[9];
    const float* Wjx2 = (const float*)d_in[10];
    const float* bjx2 = (const float*)d_in[11];
    const float* Wjh2 = (const float*)d_in[12];
    const float* bjh2 = (const float*)d_in[13];
    const float* Wkx2 = (const float*)d_in[14];
    const float* bkx2 = (const float*)d_in[15];
    const float* Wkh2 = (const float*)d_in[16];
    const float* bkh2 = (const float*)d_in[17];
    const float* Wwin = (const float*)d_in[18];
    const float* bwin = (const float*)d_in[19];
    const float* Wlin = (const float*)d_in[20];
    const float* blin = (const float*)d_in[21];

    cudaFuncSetAttribute(scan_chunk, cudaFuncAttributeMaxDynamicSharedMemorySize, SMEM_TOTAL);

    pack_kernel<<<1702, 256>>>(Wjx1, Wkx1, Wjh1, Wkh1, Wjx2, Wkx2, Wjh2, Wkh2);
    for (int ch = 0; ch < NCHUNK_; ++ch)
        scan_chunk<<<64, NT_, SMEM_TOTAL>>>(x, cvec, Wwin, bwin,
                                            bjx1, bjh1, bkx1, bkh1,
                                            bjx2, bjh2, bkx2, bkh2,
                                            ch * TCH_);
    head_kernel<<<(B_ * T_) / ROWS_, 128>>>(Wlin, blin, (float*)d_out);
}

// round 8
// speedup vs baseline: 4.8009x; 1.5598x over previous
#include <cuda_runtime.h>
#include <cstdint>

// Problem dims
#define B_    128
#define T_    600
#define U_    96
#define K_    10
#define CD_   80
#define S_    512
#define OUT_  121

// Scan config: 32 clusters x 4 CTAs, G=4 batches/cluster, 128 cols/CTA,
// NT=512 = 64 colpairs x 8 row-splits. Double-buffered state (parity per step).
#define G_     4
#define CSZ_   4
#define CPC_   64        // colpairs per CTA
#define RS_    8         // row splits
#define NT_    512
#define TCH_   75
#define NCHUNK_ 8
#define ROWS_  16

typedef unsigned long long ULL;

// ---------------- device scratch (allocation-free) ----------------
__device__ float g_ys[(size_t)B_ * T_ * S_];
// packed quad weights: [row][colpair] = (wj_c, wj_c+1, wk_c, wk_c+1)
__device__ float4 g_qw1x[83  * 256];
__device__ float4 g_qw1h[512 * 256];
__device__ float4 g_qw2x[595 * 256];
__device__ float4 g_qw2h[512 * 256];
// chunk-persistent state
__device__ float g_h1[B_][S_], g_h2[B_][S_], g_h3[B_][S_];
__device__ float g_kap[B_][K_];
__device__ float g_w[B_][CD_];

// ---------------- smem layout (bytes) ----------------
// H*: [2 parity][4 batch][512] dup-pair ULL = 2*16384
#define OFF_H1   0
#define OFF_H2   32768
#define OFF_H3   65536
#define OFF_W    98304      // [2][4][80] ULL = 2*2560
#define OFF_XT   103424     // [4][4] ULL = 128
#define OFF_RED  103552     // [64 cp][7 writers][8 ULL] = 28672
#define OFF_ATT  132224     // 30*16 floats = 1920
#define OFF_KG   134144     // 30 floats (pad 128)
#define OFF_PHI  134272     // 96 floats = 384
#define OFF_KAP  134656     // 10 floats (pad 64)
#define OFF_AL   134720
#define OFF_BE   134784
#define SMEM_TOTAL 134912

#define HPAR_ 2048          // parity stride in ULL for H arrays (4*512)
#define WPAR_ 320           // parity stride in ULL for W (4*80)

// ---------------- helpers ----------------
__device__ __forceinline__ float sigf(float x) { return 1.0f / (1.0f + expf(-x)); }
__device__ __forceinline__ void ffma2(ULL& d, ULL a, ULL b) {
    asm("fma.rn.f32x2 %0, %1, %2, %0;" : "+l"(d) : "l"(a), "l"(b));
}
__device__ __forceinline__ ULL add2(ULL a, ULL b) {
    ULL d; asm("add.rn.f32x2 %0, %1, %2;" : "=l"(d) : "l"(a), "l"(b)); return d;
}
__device__ __forceinline__ float2 up2(ULL v) {
    float2 r; asm("mov.b64 {%0,%1}, %2;" : "=f"(r.x), "=f"(r.y) : "l"(v)); return r;
}
__device__ __forceinline__ ULL pk2(float v) {
    ULL d; asm("mov.b64 %0, {%1, %1};" : "=l"(d) : "f"(v)); return d;
}
__device__ __forceinline__ ULL pk2x(float a, float b) {
    ULL d; asm("mov.b64 %0, {%1, %2};" : "=l"(d) : "f"(a), "f"(b)); return d;
}
__device__ __forceinline__ uint32_t cvta_smem(const void* p) {
    uint32_t a;
    asm("{ .reg .u64 t; cvta.to.shared.u64 t, %1; cvt.u32.u64 %0, t; }" : "=r"(a) : "l"(p));
    return a;
}
__device__ __forceinline__ uint32_t mapa32(uint32_t a, uint32_t r) {
    uint32_t d; asm("mapa.shared::cluster.u32 %0, %1, %2;" : "=r"(d) : "r"(a), "r"(r)); return d;
}
__device__ __forceinline__ void st_peer64(uint32_t a, ULL v) {
    asm volatile("st.shared::cluster.u64 [%0], %1;" :: "r"(a), "l"(v) : "memory");
}
__device__ __forceinline__ void cluster_sync() {
    asm volatile("barrier.cluster.arrive.aligned;" ::: "memory");
    asm volatile("barrier.cluster.wait.aligned;" ::: "memory");
}
__device__ __forceinline__ ulonglong2 ldq(const float4* p) {
    return __ldcg(reinterpret_cast<const ulonglong2*>(p));
}
__device__ __forceinline__ ulonglong2 ldsp(const ULL* p) {   // LDS.128 of 2 dup-pairs
    return *reinterpret_cast<const ulonglong2*>(p);
}

// 4-batch span, 2 rows/iter. ASTR = activation batch stride (ULL elems).
template<int ASTR>
__device__ __forceinline__ void span4p(const float4* __restrict__ q,
                                       const ULL* __restrict__ a,
                                       int lo, int hi, ULL* j, ULL* k)
{
#pragma unroll 2
    for (int i = lo; i < hi; i += 2) {
        ulonglong2 w0 = ldq(q + (size_t)i * 256);
        ulonglong2 w1 = ldq(q + (size_t)(i + 1) * 256);
        ulonglong2 v0 = ldsp(a + 0 * ASTR + i);
        ulonglong2 v1 = ldsp(a + 1 * ASTR + i);
        ulonglong2 v2 = ldsp(a + 2 * ASTR + i);
        ulonglong2 v3 = ldsp(a + 3 * ASTR + i);
        ffma2(j[0], v0.x, w0.x); ffma2(k[0], v0.x, w0.y);
        ffma2(j[1], v1.x, w0.x); ffma2(k[1], v1.x, w0.y);
        ffma2(j[2], v2.x, w0.x); ffma2(k[2], v2.x, w0.y);
        ffma2(j[3], v3.x, w0.x); ffma2(k[3], v3.x, w0.y);
        ffma2(j[0], v0.y, w1.x); ffma2(k[0], v0.y, w1.y);
        ffma2(j[1], v1.y, w1.x); ffma2(k[1], v1.y, w1.y);
        ffma2(j[2], v2.y, w1.x); ffma2(k[2], v2.y, w1.y);
        ffma2(j[3], v3.y, w1.x); ffma2(k[3], v3.y, w1.y);
    }
}

// dual-state 4-batch span (one weight stream -> h2 AND h3 partials)
__device__ __forceinline__ void span8p(const float4* __restrict__ q,
                                       const ULL* __restrict__ a2,
                                       const ULL* __restrict__ a3,
                                       int lo, int hi,
                                       ULL* j2, ULL* k2, ULL* j3, ULL* k3)
{
#pragma unroll 2
    for (int i = lo; i < hi; i += 2) {
        ulonglong2 w0 = ldq(q + (size_t)i * 256);
        ulonglong2 w1 = ldq(q + (size_t)(i + 1) * 256);
        ulonglong2 u0 = ldsp(a2 + 0 * 512 + i);
        ulonglong2 u1 = ldsp(a2 + 1 * 512 + i);
        ulonglong2 u2 = ldsp(a2 + 2 * 512 + i);
        ulonglong2 u3 = ldsp(a2 + 3 * 512 + i);
        ffma2(j2[0], u0.x, w0.x); ffma2(k2[0], u0.x, w0.y);
        ffma2(j2[1], u1.x, w0.x); ffma2(k2[1], u1.x, w0.y);
        ffma2(j2[2], u2.x, w0.x); ffma2(k2[2], u2.x, w0.y);
        ffma2(j2[3], u3.x, w0.x); ffma2(k2[3], u3.x, w0.y);
        ffma2(j2[0], u0.y, w1.x); ffma2(k2[0], u0.y, w1.y);
        ffma2(j2[1], u1.y, w1.x); ffma2(k2[1], u1.y, w1.y);
        ffma2(j2[2], u2.y, w1.x); ffma2(k2[2], u2.y, w1.y);
        ffma2(j2[3], u3.y, w1.x); ffma2(k2[3], u3.y, w1.y);
        ulonglong2 s0 = ldsp(a3 + 0 * 512 + i);
        ulonglong2 s1 = ldsp(a3 + 1 * 512 + i);
        ulonglong2 s2 = ldsp(a3 + 2 * 512 + i);
        ulonglong2 s3 = ldsp(a3 + 3 * 512 + i);
        ffma2(j3[0], s0.x, w0.x); ffma2(k3[0], s0.x, w0.y);
        ffma2(j3[1], s1.x, w0.x); ffma2(k3[1], s1.x, w0.y);
        ffma2(j3[2], s2.x, w0.x); ffma2(k3[2], s2.x, w0.y);
        ffma2(j3[3], s3.x, w0.x); ffma2(k3[3], s3.x, w0.y);
        ffma2(j3[0], s0.y, w1.x); ffma2(k3[0], s0.y, w1.y);
        ffma2(j3[1], s1.y, w1.x); ffma2(k3[1], s1.y, w1.y);
        ffma2(j3[2], s2.y, w1.x); ffma2(k3[2], s2.y, w1.y);
        ffma2(j3[3], s3.y, w1.x); ffma2(k3[3], s3.y, w1.y);
    }
}

// xt rows (3)
__device__ __forceinline__ void span_xt(const float4* __restrict__ q,
                                        const ULL* __restrict__ XT, ULL* j, ULL* k)
{
#pragma unroll
    for (int i = 0; i < 3; ++i) {
        ulonglong2 w = ldq(q + (size_t)i * 256);
        ULL v0 = XT[0 * 4 + i], v1 = XT[1 * 4 + i], v2 = XT[2 * 4 + i], v3 = XT[3 * 4 + i];
        ffma2(j[0], v0, w.x); ffma2(k[0], v0, w.y);
        ffma2(j[1], v1, w.x); ffma2(k[1], v1, w.y);
        ffma2(j[2], v2, w.x); ffma2(k[2], v2, w.y);
        ffma2(j[3], v3, w.x); ffma2(k[3], v3, w.y);
    }
}

// ---------------- weight packing prep ----------------
__global__ void pack_kernel(const float* __restrict__ Wjx1, const float* __restrict__ Wkx1,
                            const float* __restrict__ Wjh1, const float* __restrict__ Wkh1,
                            const float* __restrict__ Wjx2, const float* __restrict__ Wkx2,
                            const float* __restrict__ Wjh2, const float* __restrict__ Wkh2)
{
    int r = blockIdx.x, cp = threadIdx.x, c = cp * 2;
    const float *wj, *wk; float4* dst; int rr;
    if (r < 83)        { rr = r;        wj = Wjx1; wk = Wkx1; dst = g_qw1x; }
    else if (r < 595)  { rr = r - 83;   wj = Wjh1; wk = Wkh1; dst = g_qw1h; }
    else if (r < 1190) { rr = r - 595;  wj = Wjx2; wk = Wkx2; dst = g_qw2x; }
    else               { rr = r - 1190; wj = Wjh2; wk = Wkh2; dst = g_qw2h; }
    dst[(size_t)rr * 256 + cp] =
        make_float4(wj[(size_t)rr * S_ + c], wj[(size_t)rr * S_ + c + 1],
                    wk[(size_t)rr * S_ + c], wk[(size_t)rr * S_ + c + 1]);
}

// ---------------- scan chunk kernel (4-CTA clusters) ----------------
__global__ void __launch_bounds__(NT_, 1) __cluster_dims__(CSZ_, 1, 1)
scan_chunk(const float* __restrict__ x, const float* __restrict__ c_vec,
           const float* __restrict__ W_win, const float* __restrict__ b_win,
           const float* __restrict__ b_jx1, const float* __restrict__ b_jh1,
           const float* __restrict__ b_kx1, const float* __restrict__ b_kh1,
           const float* __restrict__ b_jx2, const float* __restrict__ b_jh2,
           const float* __restrict__ b_kx2, const float* __restrict__ b_kh2,
           int t0)
{
    extern __shared__ char sm[];
    ULL*   H1b = (ULL*)(sm + OFF_H1);
    ULL*   H2b = (ULL*)(sm + OFF_H2);
    ULL*   H3b = (ULL*)(sm + OFF_H3);
    ULL*   Wb  = (ULL*)(sm + OFF_W);
    ULL*   XTp = (ULL*)(sm + OFF_XT);
    ULL*   RED = (ULL*)(sm + OFF_RED);     // [64][7][8]
    float* ATT = (float*)(sm + OFF_ATT);
    float* KG  = (float*)(sm + OFF_KG);
    float* PHI = (float*)(sm + OFF_PHI);
    float* KAP = (float*)(sm + OFF_KAP);
    float* AL  = (float*)(sm + OFF_AL);
    float* BE  = (float*)(sm + OFF_BE);

    const int tid = threadIdx.x;
    uint32_t rank; asm("mov.u32 %0, %%cluster_ctarank;" : "=r"(rank));
    const int cl  = blockIdx.x >> 2;       // cluster id 0..31
    const int g0  = cl * G_;
    const int p   = tid & (CPC_ - 1);      // colpair within CTA 0..63
    const int rs  = tid >> 6;              // row split 0..7
    const int cp  = (int)rank * CPC_ + p;  // global colpair 0..255
    const int c   = cp * 2;                // global col
    const int qb  = rs * 64;               // 64-row window base for 512-row spans
    const int o64 = (cl * 8) & 63;         // stagger inside the 64-row window

    const uint32_t lbase = cvta_smem(sm);
    uint32_t pb[3];
#pragma unroll
    for (int i = 0; i < 3; ++i) pb[i] = mapa32(lbase, (rank + 1 + i) & 3);

    // ---- restore / init state into parity pt0 ----
    const int pt0 = t0 & 1;
    if (t0 == 0) {
        for (int idx = tid; idx < G_ * S_; idx += NT_) {
            H1b[idx] = 0; H2b[idx] = 0; H3b[idx] = 0;
        }
        for (int idx = tid; idx < G_ * CD_; idx += NT_) Wb[idx] = 0;
        if (tid < K_) KAP[tid] = 0.f;
    } else {
        for (int idx = tid; idx < G_ * S_; idx += NT_) {
            int b = idx >> 9, i = idx & 511;
            H1b[pt0 * HPAR_ + idx] = pk2(g_h1[g0 + b][i]);
            H2b[pt0 * HPAR_ + idx] = pk2(g_h2[g0 + b][i]);
            H3b[pt0 * HPAR_ + idx] = pk2(g_h3[g0 + b][i]);
        }
        for (int idx = tid; idx < G_ * CD_; idx += NT_)
            Wb[pt0 * WPAR_ + idx] = pk2(g_w[g0 + idx / CD_][idx % CD_]);
        if (tid < K_) KAP[tid] = g_kap[g0 + rank][tid];
    }
    __syncthreads();

    // fused biases for this thread's col-pair
    const ULL bj1 = pk2x(b_jx1[c] + b_jh1[c], b_jx1[c + 1] + b_jh1[c + 1]);
    const ULL bk1 = pk2x(b_kx1[c] + b_kh1[c], b_kx1[c + 1] + b_kh1[c + 1]);
    const ULL bj2 = pk2x(b_jx2[c] + b_jh2[c], b_jx2[c + 1] + b_jh2[c + 1]);
    const ULL bk2 = pk2x(b_kx2[c] + b_kh2[c], b_kx2[c + 1] + b_kh2[c + 1]);

    const float4* q1x  = g_qw1x + cp;              // rows 0-2 xt
    const float4* q1w  = g_qw1x + 3 * 256 + cp;    // rows 3-82 w
    const float4* q1h  = g_qw1h + cp;
    const float4* q2x  = g_qw2x + cp;
    const float4* q2hh = g_qw2x + 3 * 256 + cp;    // rows 3-514 h input
    const float4* q2w  = g_qw2x + 515 * 256 + cp;  // rows 515-594 w input
    const float4* qh2  = g_qw2h + cp;

    ULL* myRED = RED + p * 56 + (rs - 1) * 8;      // valid for rs>=1

    for (int t = t0; t < t0 + TCH_; ++t) {
        const int pt = t & 1;
        const ULL* H1o = H1b + pt * HPAR_;       ULL* H1n = H1b + (pt ^ 1) * HPAR_;
        const ULL* H2o = H2b + pt * HPAR_;       ULL* H2n = H2b + (pt ^ 1) * HPAR_;
        const ULL* H3o = H3b + pt * HPAR_;       ULL* H3n = H3b + (pt ^ 1) * HPAR_;
        const ULL* Wo  = Wb + pt * WPAR_;        ULL* Wn  = Wb + (pt ^ 1) * WPAR_;
        const uint32_t offH1n = OFF_H1 + (pt ^ 1) * 16384;
        const uint32_t offH2n = OFF_H2 + (pt ^ 1) * 16384;
        const uint32_t offH3n = OFF_H3 + (pt ^ 1) * 16384;
        const uint32_t offWn  = OFF_W + (pt ^ 1) * 2560;

        if (tid < G_ * 3) {
            int b = tid / 3, i = tid % 3;
            XTp[b * 4 + i] = pk2(x[((size_t)(g0 + b) * T_ + t) * 3 + i]);
        }
        __syncthreads();

        // ---- Q-pass: Wh2 over h2_old & h3_old (shared weight stream) ----
        ULL j2[4] = {0,0,0,0}, k2[4] = {0,0,0,0}, j3[4] = {0,0,0,0}, k3[4] = {0,0,0,0};
        span8p(qh2, H2o, H3o, qb + o64, qb + 64, j2, k2, j3, k3);
        span8p(qh2, H2o, H3o, qb, qb + o64, j2, k2, j3, k3);

        // ---------------- rnn1 ----------------
        {
            ULL j1[4] = {0,0,0,0}, k1[4] = {0,0,0,0};
            if (rs == 0) span_xt(q1x, XTp, j1, k1);
            span4p<CD_>(q1w, Wo, rs * 10, rs * 10 + 10, j1, k1);
            span4p<512>(q1h, H1o, qb + o64, qb + 64, j1, k1);
            span4p<512>(q1h, H1o, qb, qb + o64, j1, k1);
            if (rs >= 1) {
#pragma unroll
                for (int b = 0; b < 4; ++b) { myRED[b] = j1[b]; myRED[4 + b] = k1[b]; }
            }
            __syncthreads();
            if (rs == 0) {
#pragma unroll
                for (int b = 0; b < 4; ++b) {
                    ULL jj = add2(j1[b], bj1), kk = add2(k1[b], bk1);
#pragma unroll
                    for (int w = 0; w < 7; ++w) {
                        jj = add2(jj, RED[p * 56 + w * 8 + b]);
                        kk = add2(kk, RED[p * 56 + w * 8 + 4 + b]);
                    }
                    float2 jv = up2(jj), kv = up2(kk);
                    float h0 = ((const float*)H1o)[(b * 512 + c) * 2];
                    float h1o_ = ((const float*)H1o)[(b * 512 + c + 1) * 2];
                    float n0 = sigf(jv.x) * (1.f - h0) + (1.f - sigf(kv.x)) * h0;
                    float n1 = sigf(jv.y) * (1.f - h1o_) + (1.f - sigf(kv.y)) * h1o_;
                    ULL d0 = pk2(n0), d1 = pk2(n1);
                    H1n[b * 512 + c] = d0; H1n[b * 512 + c + 1] = d1;
#pragma unroll
                    for (int pr = 0; pr < 3; ++pr) {
                        st_peer64(pb[pr] + offH1n + (b * 512 + c) * 8, d0);
                        st_peer64(pb[pr] + offH1n + (b * 512 + c + 1) * 8, d1);
                    }
                }
            }
        }
        cluster_sync();   // A: h1_new visible everywhere

        // ---------------- attention (this CTA: batch g0 + rank) ----------------
        if (tid < 480) {
            int oo = tid % 30, seg = tid / 30;      // 16 segments x 32 rows
            const float* hh = (const float*)H1n + (size_t)rank * 1024;
            int base = seg * 32;
            float a0 = 0.f, a1 = 0.f;
#pragma unroll 4
            for (int i = 0; i < 32; i += 2) {
                a0 = fmaf(hh[(base + i) * 2],     W_win[(size_t)(base + i) * 30 + oo],     a0);
                a1 = fmaf(hh[(base + i + 1) * 2], W_win[(size_t)(base + i + 1) * 30 + oo], a1);
            }
            ATT[oo * 16 + seg] = a0 + a1;
        }
        __syncthreads();
        if (tid < 30) {
            float s = 0.f;
#pragma unroll
            for (int q = 0; q < 16; ++q) s += ATT[tid * 16 + q];
            KG[tid] = s + b_win[tid];
        }
        __syncthreads();
        if (tid < K_) {
            AL[tid] = expf(KG[tid]);
            BE[tid] = expf(KG[K_ + tid]);
            KAP[tid] += expf(KG[2 * K_ + tid]);
        }
        __syncthreads();
        if (tid < U_) {
            float uu = (float)tid, s = 0.f;
#pragma unroll
            for (int kk = 0; kk < K_; ++kk) {
                float d = KAP[kk] - uu;
                s += AL[kk] * expf(-BE[kk] * d * d);
            }
            PHI[tid] = s;
        }
        __syncthreads();
        if (tid < CD_) {
            const float* cv = c_vec + ((size_t)(g0 + rank) * U_) * CD_ + tid;
            float a0 = 0.f, a1 = 0.f;
#pragma unroll 4
            for (int u = 0; u < U_; u += 2) {
                a0 = fmaf(PHI[u],     cv[(size_t)u * CD_],       a0);
                a1 = fmaf(PHI[u + 1], cv[(size_t)(u + 1) * CD_], a1);
            }
            ULL d = pk2(a0 + a1);
            Wn[rank * CD_ + tid] = d;
#pragma unroll
            for (int pr = 0; pr < 3; ++pr)
                st_peer64(pb[pr] + offWn + (rank * CD_ + tid) * 8, d);
        }
        cluster_sync();   // B: w_new visible everywhere

        // ---- shared xt+w partial for rnn2 & rnn3 ----
        ULL pj[4] = {0,0,0,0}, pk_[4] = {0,0,0,0};
        if (rs == 0) span_xt(q2x, XTp, pj, pk_);
        span4p<CD_>(q2w, Wn, rs * 10, rs * 10 + 10, pj, pk_);

        // ---------------- rnn2 ----------------
        span4p<512>(q2hh, H1n, qb + o64, qb + 64, j2, k2);
        span4p<512>(q2hh, H1n, qb, qb + o64, j2, k2);
        if (rs >= 1) {
#pragma unroll
            for (int b = 0; b < 4; ++b) {
                myRED[b]     = add2(j2[b], pj[b]);
                myRED[4 + b] = add2(k2[b], pk_[b]);
            }
        }
        __syncthreads();
        if (rs == 0) {
#pragma unroll
            for (int b = 0; b < 4; ++b) {
                ULL jj = add2(add2(j2[b], pj[b]), bj2);
                ULL kk = add2(add2(k2[b], pk_[b]), bk2);
#pragma unroll
                for (int w = 0; w < 7; ++w) {
                    jj = add2(jj, RED[p * 56 + w * 8 + b]);
                    kk = add2(kk, RED[p * 56 + w * 8 + 4 + b]);
                }
                float2 jv = up2(jj), kv = up2(kk);
                float h0 = ((const float*)H2o)[(b * 512 + c) * 2];
                float h1o_ = ((const float*)H2o)[(b * 512 + c + 1) * 2];
                float n0 = sigf(jv.x) * (1.f - h0) + (1.f - sigf(kv.x)) * h0;
                float n1 = sigf(jv.y) * (1.f - h1o_) + (1.f - sigf(kv.y)) * h1o_;
                ULL d0 = pk2(n0), d1 = pk2(n1);
                H2n[b * 512 + c] = d0; H2n[b * 512 + c + 1] = d1;
#pragma unroll
                for (int pr = 0; pr < 3; ++pr) {
                    st_peer64(pb[pr] + offH2n + (b * 512 + c) * 8, d0);
                    st_peer64(pb[pr] + offH2n + (b * 512 + c + 1) * 8, d1);
                }
            }
        }
        cluster_sync();   // C: h2_new visible

        // ---------------- rnn3 (rnn2 weights reused) ----------------
        span4p<512>(q2hh, H2n, qb + o64, qb + 64, j3, k3);
        span4p<512>(q2hh, H2n, qb, qb + o64, j3, k3);
        if (rs >= 1) {
#pragma unroll
            for (int b = 0; b < 4; ++b) {
                myRED[b]     = add2(j3[b], pj[b]);
                myRED[4 + b] = add2(k3[b], pk_[b]);
            }
        }
        __syncthreads();
        if (rs == 0) {
#pragma unroll
            for (int b = 0; b < 4; ++b) {
                ULL jj = add2(add2(j3[b], pj[b]), bj2);
                ULL kk = add2(add2(k3[b], pk_[b]), bk2);
#pragma unroll
                for (int w = 0; w < 7; ++w) {
                    jj = add2(jj, RED[p * 56 + w * 8 + b]);
                    kk = add2(kk, RED[p * 56 + w * 8 + 4 + b]);
                }
                float2 jv = up2(jj), kv = up2(kk);
                float h0 = ((const float*)H3o)[(b * 512 + c) * 2];
                float h1o_ = ((const float*)H3o)[(b * 512 + c + 1) * 2];
                float n0 = sigf(jv.x) * (1.f - h0) + (1.f - sigf(kv.x)) * h0;
                float n1 = sigf(jv.y) * (1.f - h1o_) + (1.f - sigf(kv.y)) * h1o_;
                ULL d0 = pk2(n0), d1 = pk2(n1);
                H3n[b * 512 + c] = d0; H3n[b * 512 + c + 1] = d1;
#pragma unroll
                for (int pr = 0; pr < 3; ++pr) {
                    st_peer64(pb[pr] + offH3n + (b * 512 + c) * 8, d0);
                    st_peer64(pb[pr] + offH3n + (b * 512 + c + 1) * 8, d1);
                }
                *reinterpret_cast<float2*>(g_ys + ((size_t)(g0 + b) * T_ + t) * S_ + c) =
                    make_float2(n0, n1);
            }
        }
        cluster_sync();   // D: h3_new visible (next step's Q-pass reads it)
    }

    // ---- save state: CTA saves its 128-col slice for 4 batches ----
    const int ptE = (t0 + TCH_) & 1;
    for (int idx = tid; idx < G_ * 128; idx += NT_) {
        int b = idx >> 7, ii = idx & 127, col = (int)rank * 128 + ii;
        g_h1[g0 + b][col] = ((const float*)(H1b + ptE * HPAR_))[(b * 512 + col) * 2];
        g_h2[g0 + b][col] = ((const float*)(H2b + ptE * HPAR_))[(b * 512 + col) * 2];
        g_h3[g0 + b][col] = ((const float*)(H3b + ptE * HPAR_))[(b * 512 + col) * 2];
    }
    if (tid < CD_)
        g_w[g0 + rank][tid] = ((const float*)(Wb + ptE * WPAR_))[(rank * CD_ + tid) * 2];
    if (tid < K_) g_kap[g0 + rank][tid] = KAP[tid];
}

// ---------------- output head ----------------
__global__ void __launch_bounds__(128, 4)
head_kernel(const float* __restrict__ W_lin, const float* __restrict__ b_lin,
            float* __restrict__ out)
{
    __shared__ float tile[ROWS_][S_];
    const int tid = threadIdx.x;
    const size_t row0 = (size_t)blockIdx.x * ROWS_;

    for (int idx = tid; idx < ROWS_ * S_; idx += 128)
        (&tile[0][0])[idx] = __ldcg(g_ys + row0 * S_ + idx);
    __syncthreads();

    if (tid < OUT_) {
        float acc[ROWS_];
#pragma unroll
        for (int r = 0; r < ROWS_; ++r) acc[r] = 0.f;
#pragma unroll 4
        for (int s = 0; s < S_; ++s) {
            float wv = __ldcg(W_lin + (size_t)s * OUT_ + tid);
#pragma unroll
            for (int r = 0; r < ROWS_; ++r)
                acc[r] = fmaf(tile[r][s], wv, acc[r]);
        }
        float bb = b_lin[tid];
#pragma unroll
        for (int r = 0; r < ROWS_; ++r)
            out[(row0 + r) * OUT_ + tid] = acc[r] + bb;
    }
}

extern "C" void kernel_launch(void* const* d_in, const int* in_sizes, int n_in,
                              void* d_out, int out_size)
{
    const float* x    = (const float*)d_in[0];
    const float* cvec = (const float*)d_in[1];
    const float* Wjx1 = (const float*)d_in[2];
    const float* bjx1 = (const float*)d_in[3];
    const float* Wjh1 = (const float*)d_in[4];
    const float* bjh1 = (const float*)d_in[5];
    const float* Wkx1 = (const float*)d_in[6];
    const float* bkx1 = (const float*)d_in[7];
    const float* Wkh1 = (const float*)d_in[8];
    const float* bkh1 = (const float*)d_in[9];
    const float* Wjx2 = (const float*)d_in[10];
    const float* bjx2 = (const float*)d_in[11];
    const float* Wjh2 = (const float*)d_in[12];
    const float* bjh2 = (const float*)d_in[13];
    const float* Wkx2 = (const float*)d_in[14];
    const float* bkx2 = (const float*)d_in[15];
    const float* Wkh2 = (const float*)d_in[16];
    const float* bkh2 = (const float*)d_in[17];
    const float* Wwin = (const float*)d_in[18];
    const float* bwin = (const float*)d_in[19];
    const float* Wlin = (const float*)d_in[20];
    const float* blin = (const float*)d_in[21];

    cudaFuncSetAttribute(scan_chunk, cudaFuncAttributeMaxDynamicSharedMemorySize, SMEM_TOTAL);

    pack_kernel<<<1702, 256>>>(Wjx1, Wkx1, Wjh1, Wkh1, Wjx2, Wkx2, Wjh2, Wkh2);
    for (int ch = 0; ch < NCHUNK_; ++ch)
        scan_chunk<<<128, NT_, SMEM_TOTAL>>>(x, cvec, Wwin, bwin,
                                             bjx1, bjh1, bkx1, bkh1,
                                             bjx2, bjh2, bkx2, bkh2,
                                             ch * TCH_);
    head_kernel<<<(B_ * T_) / ROWS_, 128>>>(Wlin, blin, (float*)d_out);
}